// round 1
// baseline (speedup 1.0000x reference)
#include <cuda_runtime.h>
#include <math.h>

// ---------------- problem constants (fixed by the dataset) ----------------
#define Bq    4
#define LIN   13294
#define MTOK  (Bq * LIN)      // 53176 rows for all GEMMs
#define DMODEL 256
#define NHEAD 8
#define NLVL  4
#define NPTS  4
#define DH    32
#define DFF   1024

// ---------------- scratch (device globals; no runtime allocation) ----------
__device__ float g_q    [(size_t)MTOK * DMODEL];
__device__ float g_value[(size_t)MTOK * DMODEL];
__device__ float g_offs [(size_t)MTOK * DMODEL];   // reused later as ff2 output
__device__ float g_aw   [(size_t)MTOK * 128];
__device__ float g_msda [(size_t)MTOK * DMODEL];
__device__ float g_x    [(size_t)MTOK * DMODEL];
__device__ float g_ffh  [(size_t)MTOK * DFF];

// ---------------- elementwise add (q = src + pos), float4 ------------------
__global__ void add_kernel(const float* __restrict__ a, const float* __restrict__ b,
                           float* __restrict__ c, int n4)
{
    int i = blockIdx.x * blockDim.x + threadIdx.x;
    int stride = gridDim.x * blockDim.x;
    const float4* a4 = (const float4*)a;
    const float4* b4 = (const float4*)b;
    float4* c4 = (float4*)c;
    for (; i < n4; i += stride) {
        float4 x = a4[i], y = b4[i];
        x.x += y.x; x.y += y.y; x.z += y.z; x.w += y.w;
        c4[i] = x;
    }
}

// ---------------- SGEMM: C[M,N] = A[M,K] @ W[K,N] + bias, optional ReLU ----
// 64x64 tile, BK=16, 256 threads, 4x4 per thread, float4 global loads.
#define BM 64
#define BN 64
#define BK 16

__global__ __launch_bounds__(256)
void gemm_bias_kernel(const float* __restrict__ A, const float* __restrict__ W,
                      const float* __restrict__ bias, float* __restrict__ C,
                      int M, int K, int N, int relu)
{
    __shared__ __align__(16) float As[BK][BM];
    __shared__ __align__(16) float Ws[BK][BN];

    const int tid = threadIdx.x;
    const int tx = tid & 15;        // 0..15 -> N micro
    const int ty = tid >> 4;        // 0..15 -> M micro
    const int row0 = blockIdx.y * BM;
    const int col0 = blockIdx.x * BN;

    // A tile load: m = tid/4 (0..63), k = (tid&3)*4 (float4 along K)
    const int am = tid >> 2;
    const int ak = (tid & 3) * 4;
    // W tile load: k = tid/16 (0..15), n = (tid&15)*4 (float4 along N)
    const int wk = tid >> 4;
    const int wn = (tid & 15) * 4;

    float acc[4][4] = {};

    for (int k0 = 0; k0 < K; k0 += BK) {
        float4 av = make_float4(0.f, 0.f, 0.f, 0.f);
        int arow = row0 + am;
        if (arow < M)
            av = *reinterpret_cast<const float4*>(&A[(size_t)arow * K + k0 + ak]);
        As[ak + 0][am] = av.x;
        As[ak + 1][am] = av.y;
        As[ak + 2][am] = av.z;
        As[ak + 3][am] = av.w;

        float4 wv = *reinterpret_cast<const float4*>(&W[(size_t)(k0 + wk) * N + col0 + wn]);
        *reinterpret_cast<float4*>(&Ws[wk][wn]) = wv;

        __syncthreads();
#pragma unroll
        for (int k = 0; k < BK; k++) {
            float4 a4 = *reinterpret_cast<const float4*>(&As[k][ty * 4]);
            float4 w4 = *reinterpret_cast<const float4*>(&Ws[k][tx * 4]);
            float a[4] = {a4.x, a4.y, a4.z, a4.w};
            float w[4] = {w4.x, w4.y, w4.z, w4.w};
#pragma unroll
            for (int i = 0; i < 4; i++)
#pragma unroll
                for (int j = 0; j < 4; j++)
                    acc[i][j] = fmaf(a[i], w[j], acc[i][j]);
        }
        __syncthreads();
    }

#pragma unroll
    for (int i = 0; i < 4; i++) {
        int r = row0 + ty * 4 + i;
        if (r >= M) continue;
#pragma unroll
        for (int j = 0; j < 4; j++) {
            int c = col0 + tx * 4 + j;
            float v = acc[i][j] + bias[c];
            if (relu) v = fmaxf(v, 0.f);
            C[(size_t)r * N + c] = v;
        }
    }
}

// ---------------- softmax over 16 contiguous logits per (token, head) ------
__global__ void softmax16_kernel(float* __restrict__ aw, int total)
{
    int i = blockIdx.x * blockDim.x + threadIdx.x;
    if (i >= total) return;
    float* p = aw + (size_t)i * 16;
    float v[16];
    float m = -1e30f;
#pragma unroll
    for (int j = 0; j < 16; j++) { v[j] = p[j]; m = fmaxf(m, v[j]); }
    float s = 0.f;
#pragma unroll
    for (int j = 0; j < 16; j++) { v[j] = expf(v[j] - m); s += v[j]; }
    float inv = 1.f / s;
#pragma unroll
    for (int j = 0; j < 16; j++) p[j] = v[j] * inv;
}

// ---------------- MSDA bilinear sampling -----------------------------------
// block = token (53176 blocks), warp = head (8), lane = channel (32).
__global__ __launch_bounds__(256)
void msda_kernel(const float* __restrict__ value, const float* __restrict__ offs,
                 const float* __restrict__ aw, const float* __restrict__ ref,
                 const int* __restrict__ shapes, const int* __restrict__ starts,
                 float* __restrict__ out)
{
    const int tok = blockIdx.x;
    const int h = threadIdx.x >> 5;
    const int lane = threadIdx.x & 31;
    const int b = tok / LIN;

    const float* refp = ref + (size_t)tok * (NLVL * 2);
    float acc = 0.f;

#pragma unroll
    for (int l = 0; l < NLVL; l++) {
        const int Hl = shapes[l * 2 + 0];
        const int Wl = shapes[l * 2 + 1];
        const int s  = starts[l];
        const float fW = (float)Wl, fH = (float)Hl;
        const float rx = refp[l * 2 + 0];
        const float ry = refp[l * 2 + 1];

        const float* op = offs + (size_t)tok * 256 + (size_t)((h * NLVL + l) * NPTS) * 2;
        const float* ap = aw + (size_t)tok * 128 + h * 16 + l * NPTS;
        const size_t vbase = ((size_t)b * LIN + s) * DMODEL + h * DH + lane;

#pragma unroll
        for (int p = 0; p < NPTS; p++) {
            float ox = op[p * 2 + 0];
            float oy = op[p * 2 + 1];
            float a  = ap[p];
            // match reference: (ref + off/norm) * size - 0.5
            float x = (rx + ox / fW) * fW - 0.5f;
            float y = (ry + oy / fH) * fH - 0.5f;
            float x0f = floorf(x), y0f = floorf(y);
            float dx = x - x0f, dy = y - y0f;
            int x0 = (int)x0f, y0 = (int)y0f;

            float w00 = (1.f - dx) * (1.f - dy);
            float w10 = dx * (1.f - dy);
            float w01 = (1.f - dx) * dy;
            float w11 = dx * dy;

            bool xv0 = (x0 >= 0) && (x0 < Wl);
            bool xv1 = (x0 + 1 >= 0) && (x0 + 1 < Wl);
            bool yv0 = (y0 >= 0) && (y0 < Hl);
            bool yv1 = (y0 + 1 >= 0) && (y0 + 1 < Hl);

            float v00 = 0.f, v10 = 0.f, v01 = 0.f, v11 = 0.f;
            if (yv0 && xv0) v00 = value[vbase + (size_t)(y0 * Wl + x0) * DMODEL];
            if (yv0 && xv1) v10 = value[vbase + (size_t)(y0 * Wl + x0 + 1) * DMODEL];
            if (yv1 && xv0) v01 = value[vbase + (size_t)((y0 + 1) * Wl + x0) * DMODEL];
            if (yv1 && xv1) v11 = value[vbase + (size_t)((y0 + 1) * Wl + x0 + 1) * DMODEL];

            acc = fmaf(a, w00 * v00 + w10 * v10 + w01 * v01 + w11 * v11, acc);
        }
    }
    out[(size_t)tok * DMODEL + h * DH + lane] = acc;
}

// ---------------- fused residual add + LayerNorm ---------------------------
// block = token (256 threads, one per channel). out = LN(a + r) * g + b
__global__ __launch_bounds__(256)
void add_ln_kernel(const float* __restrict__ a, const float* __restrict__ r,
                   const float* __restrict__ g, const float* __restrict__ bb,
                   float* __restrict__ out)
{
    const int tok = blockIdx.x;
    const int i = threadIdx.x;
    float v = a[(size_t)tok * DMODEL + i] + r[(size_t)tok * DMODEL + i];

    __shared__ float sh[8];
    // mean
    float s = v;
#pragma unroll
    for (int o = 16; o; o >>= 1) s += __shfl_xor_sync(0xffffffffu, s, o);
    if ((i & 31) == 0) sh[i >> 5] = s;
    __syncthreads();
    float tot = 0.f;
#pragma unroll
    for (int w = 0; w < 8; w++) tot += sh[w];
    float mean = tot * (1.f / 256.f);
    __syncthreads();

    // variance
    float d = v - mean;
    float s2 = d * d;
#pragma unroll
    for (int o = 16; o; o >>= 1) s2 += __shfl_xor_sync(0xffffffffu, s2, o);
    if ((i & 31) == 0) sh[i >> 5] = s2;
    __syncthreads();
    float tot2 = 0.f;
#pragma unroll
    for (int w = 0; w < 8; w++) tot2 += sh[w];
    float var = tot2 * (1.f / 256.f);

    out[(size_t)tok * DMODEL + i] = d * rsqrtf(var + 1e-5f) * g[i] + bb[i];
}

// ---------------- launch ----------------------------------------------------
extern "C" void kernel_launch(void* const* d_in, const int* in_sizes, int n_in,
                              void* d_out, int out_size)
{
    const float* src    = (const float*)d_in[0];
    const float* pos    = (const float*)d_in[1];
    const float* refpts = (const float*)d_in[2];
    const int*   shapes = (const int*)  d_in[3];
    const int*   starts = (const int*)  d_in[4];
    const float* value_w = (const float*)d_in[5];
    const float* value_b = (const float*)d_in[6];
    const float* offs_w  = (const float*)d_in[7];
    const float* offs_b  = (const float*)d_in[8];
    const float* attn_w  = (const float*)d_in[9];
    const float* attn_b  = (const float*)d_in[10];
    const float* out_w   = (const float*)d_in[11];
    const float* out_b   = (const float*)d_in[12];
    const float* ln1_g   = (const float*)d_in[13];
    const float* ln1_b   = (const float*)d_in[14];
    const float* ff1_w   = (const float*)d_in[15];
    const float* ff1_b   = (const float*)d_in[16];
    const float* ff2_w   = (const float*)d_in[17];
    const float* ff2_b   = (const float*)d_in[18];
    const float* ln2_g   = (const float*)d_in[19];
    const float* ln2_b   = (const float*)d_in[20];
    float* outp = (float*)d_out;

    float *q, *value, *offs, *aw, *msda, *x, *ffh;
    cudaGetSymbolAddress((void**)&q,     g_q);
    cudaGetSymbolAddress((void**)&value, g_value);
    cudaGetSymbolAddress((void**)&offs,  g_offs);
    cudaGetSymbolAddress((void**)&aw,    g_aw);
    cudaGetSymbolAddress((void**)&msda,  g_msda);
    cudaGetSymbolAddress((void**)&x,     g_x);
    cudaGetSymbolAddress((void**)&ffh,   g_ffh);

    const int M = MTOK;
    const int n4 = M * DMODEL / 4;

    // 1. q = src + pos
    add_kernel<<<2048, 256>>>(src, pos, q, n4);

    dim3 blk(256);
    int gy = (M + BM - 1) / BM;

    // 2. value = q @ value_w + value_b
    gemm_bias_kernel<<<dim3(DMODEL / BN, gy), blk>>>(q, value_w, value_b, value, M, DMODEL, DMODEL, 0);
    // 3. offs = q @ offs_w + offs_b
    gemm_bias_kernel<<<dim3(DMODEL / BN, gy), blk>>>(q, offs_w, offs_b, offs, M, DMODEL, DMODEL, 0);
    // 4. attn logits -> g_aw
    gemm_bias_kernel<<<dim3(128 / BN, gy), blk>>>(q, attn_w, attn_b, aw, M, DMODEL, 128, 0);
    // 5. softmax over 16 per (token, head)
    {
        int total = M * NHEAD;
        softmax16_kernel<<<(total + 255) / 256, 256>>>(aw, total);
    }
    // 6. deformable sampling
    msda_kernel<<<M, 256>>>(value, offs, aw, refpts, shapes, starts, msda);
    // 7. src2 = msda @ out_w + out_b   (reuse 'value' buffer for src2)
    gemm_bias_kernel<<<dim3(DMODEL / BN, gy), blk>>>(msda, out_w, out_b, value, M, DMODEL, DMODEL, 0);
    // 8. x = LN(q + src2)
    add_ln_kernel<<<M, 256>>>(q, value, ln1_g, ln1_b, x);
    // 9. ffh = relu(x @ ff1_w + ff1_b)
    gemm_bias_kernel<<<dim3(DFF / BN, gy), blk>>>(x, ff1_w, ff1_b, ffh, M, DMODEL, DFF, 1);
    // 10. f = ffh @ ff2_w + ff2_b   (reuse 'offs' buffer)
    gemm_bias_kernel<<<dim3(DMODEL / BN, gy), blk>>>(ffh, ff2_w, ff2_b, offs, M, DFF, DMODEL, 0);
    // 11. out = LN(x + f)
    add_ln_kernel<<<M, 256>>>(x, offs, ln2_g, ln2_b, outp);
}

// round 3
// speedup vs baseline: 1.6856x; 1.6856x over previous
#include <cuda_runtime.h>
#include <cuda_bf16.h>
#include <cstdint>
#include <math.h>

// ---------------- problem constants ----------------
#define Bq    4
#define LIN   13294
#define MTOK  (Bq * LIN)      // 53176
#define DMODEL 256
#define NHEAD 8
#define NLVL  4
#define NPTS  4
#define DH    32
#define DFF   1024

// ---------------- scratch (device globals) ----------------
__device__ float g_q    [(size_t)MTOK * DMODEL];
__device__ __nv_bfloat16 g_qs [(size_t)MTOK * 2 * DMODEL];     // [hi|lo]
__device__ float g_value[(size_t)MTOK * DMODEL];
__device__ float g_offs [(size_t)MTOK * DMODEL];   // also reused for ff2 out
__device__ float g_aw   [(size_t)MTOK * 128];
__device__ __nv_bfloat16 g_msdas[(size_t)MTOK * 2 * DMODEL];
__device__ float g_src2 [(size_t)MTOK * DMODEL];
__device__ float g_x    [(size_t)MTOK * DMODEL];
__device__ __nv_bfloat16 g_xs [(size_t)MTOK * 2 * DMODEL];
__device__ __nv_bfloat16 g_ffhs[(size_t)MTOK * 2 * DFF];
// transposed/split weights: [N, 3K] bf16 K-major: [hi | hi | lo]
__device__ __nv_bfloat16 g_wt_value[256 * 768];
__device__ __nv_bfloat16 g_wt_offs [256 * 768];
__device__ __nv_bfloat16 g_wt_attn [128 * 768];
__device__ __nv_bfloat16 g_wt_out  [256 * 768];
__device__ __nv_bfloat16 g_wt_ff1  [1024 * 768];
__device__ __nv_bfloat16 g_wt_ff2  [256 * 3072];

// ---------------- helpers ----------------
__device__ __forceinline__ uint32_t smem_u32(const void* p) {
    uint32_t a;
    asm("{ .reg .u64 t; cvta.to.shared.u64 t, %1; cvt.u32.u64 %0, t; }" : "=r"(a) : "l"(p));
    return a;
}
#define CP_ASYNC16(dst, src) \
    asm volatile("cp.async.cg.shared.global [%0], [%1], 16;\n" :: "r"(dst), "l"(src) : "memory")
#define CP_COMMIT() asm volatile("cp.async.commit_group;\n" ::: "memory")
#define CP_WAIT(n)  asm volatile("cp.async.wait_group %0;\n" :: "n"(n) : "memory")

__device__ __forceinline__ void ldmatrix_x4(uint32_t& r0, uint32_t& r1, uint32_t& r2, uint32_t& r3, uint32_t addr) {
    asm volatile("ldmatrix.sync.aligned.m8n8.x4.shared.b16 {%0,%1,%2,%3}, [%4];"
                 : "=r"(r0), "=r"(r1), "=r"(r2), "=r"(r3) : "r"(addr));
}
__device__ __forceinline__ void mma_bf16(float* c, const uint32_t* a, const uint32_t* b) {
    asm volatile("mma.sync.aligned.m16n8k16.row.col.f32.bf16.bf16.f32 "
                 "{%0,%1,%2,%3}, {%4,%5,%6,%7}, {%8,%9}, {%0,%1,%2,%3};"
                 : "+f"(c[0]), "+f"(c[1]), "+f"(c[2]), "+f"(c[3])
                 : "r"(a[0]), "r"(a[1]), "r"(a[2]), "r"(a[3]), "r"(b[0]), "r"(b[1]));
}

// ---------------- bf16 warp-MMA GEMM ----------------
// C[M,N] = A_logical[M,Kfull] @ B[N,Kfull]^T (+bias) ; A stored [M,lda] with
// column remap: acol = (k < k2) ? k : k - k2   (the [hi|lo] / [hi|hi|lo] trick)
// Tile 128x128, BK=32, 8 warps (4 M x 2 N), cp.async double buffer.
// Output: Cf (fp32) if non-null; Cs (bf16 hi/lo split, stride 2N) if non-null.
#define PADS 40   // smem row stride in bf16 (80 bytes)

__global__ __launch_bounds__(256, 2)
void gemm_mma(const __nv_bfloat16* __restrict__ A, int lda, int k2,
              const __nv_bfloat16* __restrict__ B, int ldb,
              const float* __restrict__ bias,
              float* __restrict__ Cf, __nv_bfloat16* __restrict__ Cs,
              int M, int Kfull, int N, int relu)
{
    __shared__ __align__(16) __nv_bfloat16 sA[2][128 * PADS];
    __shared__ __align__(16) __nv_bfloat16 sB[2][128 * PADS];

    const int tid  = threadIdx.x;
    const int wid  = tid >> 5;
    const int lane = tid & 31;
    const int wm   = wid & 3;    // warp row (32 rows)
    const int wn   = wid >> 2;   // warp col (64 cols)
    const int row0 = blockIdx.y * 128;
    const int col0 = blockIdx.x * 128;

    const int NC = Kfull >> 5;   // BK = 32

    float acc[2][8][4];
#pragma unroll
    for (int i = 0; i < 2; i++)
#pragma unroll
        for (int j = 0; j < 8; j++)
#pragma unroll
            for (int t = 0; t < 4; t++) acc[i][j][t] = 0.f;

    // ---- stage loader: 512 16B-chunks each for A and B, 2+2 per thread ----
#define LOAD_STAGE(buf, cc) do {                                              \
        int _kc = (cc) << 5;                                                  \
        int _acol = (_kc < k2) ? _kc : _kc - k2;                              \
        uint32_t _dA = smem_u32(&sA[buf][0]);                                 \
        uint32_t _dB = smem_u32(&sB[buf][0]);                                 \
        _Pragma("unroll")                                                     \
        for (int _i = 0; _i < 2; ++_i) {                                      \
            int _c = tid + _i * 256;                                          \
            int _r = _c >> 2, _k8 = _c & 3;                                   \
            int _gr = row0 + _r; if (_gr >= M) _gr = M - 1;                   \
            CP_ASYNC16(_dA + (_r * PADS + _k8 * 8) * 2,                       \
                       A + (size_t)_gr * lda + _acol + _k8 * 8);              \
        }                                                                     \
        _Pragma("unroll")                                                     \
        for (int _i = 0; _i < 2; ++_i) {                                      \
            int _c = tid + _i * 256;                                          \
            int _r = _c >> 2, _k8 = _c & 3;                                   \
            CP_ASYNC16(_dB + (_r * PADS + _k8 * 8) * 2,                       \
                       B + (size_t)(col0 + _r) * ldb + _kc + _k8 * 8);        \
        }                                                                     \
    } while (0)

    LOAD_STAGE(0, 0);
    CP_COMMIT();

    for (int c = 0; c < NC; ++c) {
        const int buf = c & 1;
        if (c + 1 < NC) {
            LOAD_STAGE(buf ^ 1, c + 1);
            CP_COMMIT();
            CP_WAIT(1);
        } else {
            CP_WAIT(0);
        }
        __syncthreads();

        const uint32_t baseA = smem_u32(&sA[buf][0]);
        const uint32_t baseB = smem_u32(&sB[buf][0]);

#pragma unroll
        for (int kk = 0; kk < 32; kk += 16) {
            uint32_t a[2][4];
#pragma unroll
            for (int mt = 0; mt < 2; mt++) {
                int r = wm * 32 + mt * 16 + (lane & 15);
                int kc = kk + ((lane & 16) ? 8 : 0);
                ldmatrix_x4(a[mt][0], a[mt][1], a[mt][2], a[mt][3],
                            baseA + (r * PADS + kc) * 2);
            }
            uint32_t b[8][2];
#pragma unroll
            for (int np = 0; np < 4; np++) {
                int n = wn * 64 + np * 16 + (lane & 7) + ((lane & 16) ? 8 : 0);
                int kc = kk + ((lane & 8) ? 8 : 0);
                ldmatrix_x4(b[2 * np][0], b[2 * np][1], b[2 * np + 1][0], b[2 * np + 1][1],
                            baseB + (n * PADS + kc) * 2);
            }
#pragma unroll
            for (int mt = 0; mt < 2; mt++)
#pragma unroll
                for (int nt = 0; nt < 8; nt++)
                    mma_bf16(acc[mt][nt], a[mt], b[nt]);
        }
        __syncthreads();
    }

    // ---- epilogue ----
#pragma unroll
    for (int mt = 0; mt < 2; mt++) {
#pragma unroll
        for (int half = 0; half < 2; half++) {
            int r = row0 + wm * 32 + mt * 16 + (lane >> 2) + half * 8;
            if (r >= M) continue;
#pragma unroll
            for (int nt = 0; nt < 8; nt++) {
                int cidx = col0 + wn * 64 + nt * 8 + (lane & 3) * 2;
                float v0 = acc[mt][nt][half * 2 + 0] + bias[cidx];
                float v1 = acc[mt][nt][half * 2 + 1] + bias[cidx + 1];
                if (relu) { v0 = fmaxf(v0, 0.f); v1 = fmaxf(v1, 0.f); }
                if (Cf) {
                    float2 o = make_float2(v0, v1);
                    *reinterpret_cast<float2*>(Cf + (size_t)r * N + cidx) = o;
                }
                if (Cs) {
                    __nv_bfloat16 h0 = __float2bfloat16(v0);
                    __nv_bfloat16 h1 = __float2bfloat16(v1);
                    __nv_bfloat16 l0 = __float2bfloat16(v0 - __bfloat162float(h0));
                    __nv_bfloat16 l1 = __float2bfloat16(v1 - __bfloat162float(h1));
                    __nv_bfloat162 hv; hv.x = h0; hv.y = h1;
                    __nv_bfloat162 lv; lv.x = l0; lv.y = l1;
                    *reinterpret_cast<__nv_bfloat162*>(Cs + (size_t)r * 2 * N + cidx) = hv;
                    *reinterpret_cast<__nv_bfloat162*>(Cs + (size_t)r * 2 * N + N + cidx) = lv;
                }
            }
        }
    }
#undef LOAD_STAGE
}

// ---------------- prep kernels ----------------
__global__ void add_split_kernel(const float* __restrict__ a, const float* __restrict__ b,
                                 float* __restrict__ q, __nv_bfloat16* __restrict__ qs, int n)
{
    int i = blockIdx.x * blockDim.x + threadIdx.x;
    if (i >= n) return;
    float v = a[i] + b[i];
    q[i] = v;
    int r = i >> 8, c = i & 255;
    __nv_bfloat16 h = __float2bfloat16(v);
    float lo = v - __bfloat162float(h);
    qs[(size_t)r * 512 + c] = h;
    qs[(size_t)r * 512 + 256 + c] = __float2bfloat16(lo);
}

// W [K,N] fp32 -> Wt [N, 3K] bf16: [hi | hi | lo]
__global__ void wsplit_kernel(const float* __restrict__ W, __nv_bfloat16* __restrict__ Wt, int K_, int N_)
{
    int i = blockIdx.x * blockDim.x + threadIdx.x;
    if (i >= K_ * N_) return;
    int k = i / N_, n = i % N_;
    float v = W[i];
    __nv_bfloat16 h = __float2bfloat16(v);
    float lo = v - __bfloat162float(h);
    size_t b = (size_t)n * 3 * K_;
    Wt[b + k] = h;
    Wt[b + K_ + k] = h;
    Wt[b + 2 * K_ + k] = __float2bfloat16(lo);
}

// ---------------- softmax over 16 contiguous logits ----------------
__global__ void softmax16_kernel(float* __restrict__ aw, int total)
{
    int i = blockIdx.x * blockDim.x + threadIdx.x;
    if (i >= total) return;
    float* p = aw + (size_t)i * 16;
    float v[16];
    float m = -1e30f;
#pragma unroll
    for (int j = 0; j < 16; j++) { v[j] = p[j]; m = fmaxf(m, v[j]); }
    float s = 0.f;
#pragma unroll
    for (int j = 0; j < 16; j++) { v[j] = expf(v[j] - m); s += v[j]; }
    float inv = 1.f / s;
#pragma unroll
    for (int j = 0; j < 16; j++) p[j] = v[j] * inv;
}

// ---------------- MSDA bilinear sampling (writes bf16 hi/lo split) ---------
__global__ __launch_bounds__(256)
void msda_kernel(const float* __restrict__ value, const float* __restrict__ offs,
                 const float* __restrict__ aw, const float* __restrict__ ref,
                 const int* __restrict__ shapes, const int* __restrict__ starts,
                 __nv_bfloat16* __restrict__ outs)
{
    const int tok = blockIdx.x;
    const int h = threadIdx.x >> 5;
    const int lane = threadIdx.x & 31;
    const int b = tok / LIN;

    const float* refp = ref + (size_t)tok * (NLVL * 2);
    float acc = 0.f;

#pragma unroll
    for (int l = 0; l < NLVL; l++) {
        const int Hl = shapes[l * 2 + 0];
        const int Wl = shapes[l * 2 + 1];
        const int s  = starts[l];
        const float fW = (float)Wl, fH = (float)Hl;
        const float rx = refp[l * 2 + 0];
        const float ry = refp[l * 2 + 1];

        const float* op = offs + (size_t)tok * 256 + (size_t)((h * NLVL + l) * NPTS) * 2;
        const float* ap = aw + (size_t)tok * 128 + h * 16 + l * NPTS;
        const size_t vbase = ((size_t)b * LIN + s) * DMODEL + h * DH + lane;

#pragma unroll
        for (int p = 0; p < NPTS; p++) {
            float ox = op[p * 2 + 0];
            float oy = op[p * 2 + 1];
            float a  = ap[p];
            float x = (rx + ox / fW) * fW - 0.5f;
            float y = (ry + oy / fH) * fH - 0.5f;
            float x0f = floorf(x), y0f = floorf(y);
            float dx = x - x0f, dy = y - y0f;
            int x0 = (int)x0f, y0 = (int)y0f;

            float w00 = (1.f - dx) * (1.f - dy);
            float w10 = dx * (1.f - dy);
            float w01 = (1.f - dx) * dy;
            float w11 = dx * dy;

            bool xv0 = (x0 >= 0) && (x0 < Wl);
            bool xv1 = (x0 + 1 >= 0) && (x0 + 1 < Wl);
            bool yv0 = (y0 >= 0) && (y0 < Hl);
            bool yv1 = (y0 + 1 >= 0) && (y0 + 1 < Hl);

            float v00 = 0.f, v10 = 0.f, v01 = 0.f, v11 = 0.f;
            if (yv0 && xv0) v00 = value[vbase + (size_t)(y0 * Wl + x0) * DMODEL];
            if (yv0 && xv1) v10 = value[vbase + (size_t)(y0 * Wl + x0 + 1) * DMODEL];
            if (yv1 && xv0) v01 = value[vbase + (size_t)((y0 + 1) * Wl + x0) * DMODEL];
            if (yv1 && xv1) v11 = value[vbase + (size_t)((y0 + 1) * Wl + x0 + 1) * DMODEL];

            acc = fmaf(a, w00 * v00 + w10 * v10 + w01 * v01 + w11 * v11, acc);
        }
    }
    int ch = h * DH + lane;
    __nv_bfloat16 hh = __float2bfloat16(acc);
    outs[(size_t)tok * 512 + ch] = hh;
    outs[(size_t)tok * 512 + 256 + ch] = __float2bfloat16(acc - __bfloat162float(hh));
}

// ---------------- fused residual add + LayerNorm (+ optional split) --------
__global__ __launch_bounds__(256)
void add_ln_kernel(const float* __restrict__ a, const float* __restrict__ r,
                   const float* __restrict__ g, const float* __restrict__ bb,
                   float* __restrict__ out, __nv_bfloat16* __restrict__ outs)
{
    const int tok = blockIdx.x;
    const int i = threadIdx.x;
    float v = a[(size_t)tok * DMODEL + i] + r[(size_t)tok * DMODEL + i];

    __shared__ float sh[8];
    float s = v;
#pragma unroll
    for (int o = 16; o; o >>= 1) s += __shfl_xor_sync(0xffffffffu, s, o);
    if ((i & 31) == 0) sh[i >> 5] = s;
    __syncthreads();
    float tot = 0.f;
#pragma unroll
    for (int w = 0; w < 8; w++) tot += sh[w];
    float mean = tot * (1.f / 256.f);
    __syncthreads();

    float d = v - mean;
    float s2 = d * d;
#pragma unroll
    for (int o = 16; o; o >>= 1) s2 += __shfl_xor_sync(0xffffffffu, s2, o);
    if ((i & 31) == 0) sh[i >> 5] = s2;
    __syncthreads();
    float tot2 = 0.f;
#pragma unroll
    for (int w = 0; w < 8; w++) tot2 += sh[w];
    float var = tot2 * (1.f / 256.f);

    float o = d * rsqrtf(var + 1e-5f) * g[i] + bb[i];
    out[(size_t)tok * DMODEL + i] = o;
    if (outs) {
        __nv_bfloat16 h = __float2bfloat16(o);
        outs[(size_t)tok * 512 + i] = h;
        outs[(size_t)tok * 512 + 256 + i] = __float2bfloat16(o - __bfloat162float(h));
    }
}

// ---------------- launch ----------------
extern "C" void kernel_launch(void* const* d_in, const int* in_sizes, int n_in,
                              void* d_out, int out_size)
{
    const float* src    = (const float*)d_in[0];
    const float* pos    = (const float*)d_in[1];
    const float* refpts = (const float*)d_in[2];
    const int*   shapes = (const int*)  d_in[3];
    const int*   starts = (const int*)  d_in[4];
    const float* value_w = (const float*)d_in[5];
    const float* value_b = (const float*)d_in[6];
    const float* offs_w  = (const float*)d_in[7];
    const float* offs_b  = (const float*)d_in[8];
    const float* attn_w  = (const float*)d_in[9];
    const float* attn_b  = (const float*)d_in[10];
    const float* out_w   = (const float*)d_in[11];
    const float* out_b   = (const float*)d_in[12];
    const float* ln1_g   = (const float*)d_in[13];
    const float* ln1_b   = (const float*)d_in[14];
    const float* ff1_w   = (const float*)d_in[15];
    const float* ff1_b   = (const float*)d_in[16];
    const float* ff2_w   = (const float*)d_in[17];
    const float* ff2_b   = (const float*)d_in[18];
    const float* ln2_g   = (const float*)d_in[19];
    const float* ln2_b   = (const float*)d_in[20];
    float* outp = (float*)d_out;

    float *q, *value, *offs, *aw, *src2, *x;
    __nv_bfloat16 *qs, *msdas, *xs, *ffhs;
    __nv_bfloat16 *wtv, *wto, *wta, *wtu, *wtf1, *wtf2;
    cudaGetSymbolAddress((void**)&q,     g_q);
    cudaGetSymbolAddress((void**)&qs,    g_qs);
    cudaGetSymbolAddress((void**)&value, g_value);
    cudaGetSymbolAddress((void**)&offs,  g_offs);
    cudaGetSymbolAddress((void**)&aw,    g_aw);
    cudaGetSymbolAddress((void**)&msdas, g_msdas);
    cudaGetSymbolAddress((void**)&src2,  g_src2);
    cudaGetSymbolAddress((void**)&x,     g_x);
    cudaGetSymbolAddress((void**)&xs,    g_xs);
    cudaGetSymbolAddress((void**)&ffhs,  g_ffhs);
    cudaGetSymbolAddress((void**)&wtv,   g_wt_value);
    cudaGetSymbolAddress((void**)&wto,   g_wt_offs);
    cudaGetSymbolAddress((void**)&wta,   g_wt_attn);
    cudaGetSymbolAddress((void**)&wtu,   g_wt_out);
    cudaGetSymbolAddress((void**)&wtf1,  g_wt_ff1);
    cudaGetSymbolAddress((void**)&wtf2,  g_wt_ff2);

    const int M = MTOK;
    const int gy = (M + 127) / 128;

    // weight prep (small)
    wsplit_kernel<<<(256 * 256 + 255) / 256, 256>>>(value_w, wtv, 256, 256);
    wsplit_kernel<<<(256 * 256 + 255) / 256, 256>>>(offs_w,  wto, 256, 256);
    wsplit_kernel<<<(256 * 128 + 255) / 256, 256>>>(attn_w,  wta, 256, 128);
    wsplit_kernel<<<(256 * 256 + 255) / 256, 256>>>(out_w,   wtu, 256, 256);
    wsplit_kernel<<<(256 * 1024 + 255) / 256, 256>>>(ff1_w,  wtf1, 256, 1024);
    wsplit_kernel<<<(1024 * 256 + 255) / 256, 256>>>(ff2_w,  wtf2, 1024, 256);

    // 1. q = src + pos (+ bf16 split)
    add_split_kernel<<<(M * DMODEL + 255) / 256, 256>>>(src, pos, q, qs, M * DMODEL);

    // 2-4. projections of q
    gemm_mma<<<dim3(2, gy), 256>>>(qs, 512, 512, wtv, 768, value_b, value, nullptr, M, 768, 256, 0);
    gemm_mma<<<dim3(2, gy), 256>>>(qs, 512, 512, wto, 768, offs_b,  offs,  nullptr, M, 768, 256, 0);
    gemm_mma<<<dim3(1, gy), 256>>>(qs, 512, 512, wta, 768, attn_b,  aw,    nullptr, M, 768, 128, 0);

    // 5. softmax
    softmax16_kernel<<<(M * NHEAD + 255) / 256, 256>>>(aw, M * NHEAD);

    // 6. deformable sampling -> bf16 split directly
    msda_kernel<<<M, 256>>>(value, offs, aw, refpts, shapes, starts, msdas);

    // 7. output projection: src2 = msda @ out_w + out_b
    gemm_mma<<<dim3(2, gy), 256>>>(msdas, 512, 512, wtu, 768, out_b, src2, nullptr, M, 768, 256, 0);

    // 8. x = LN(q + src2)  (+ split xs)
    add_ln_kernel<<<M, 256>>>(q, src2, ln1_g, ln1_b, x, xs);

    // 9. ffh = relu(x @ ff1_w + ff1_b) -> split only
    gemm_mma<<<dim3(8, gy), 256>>>(xs, 512, 512, wtf1, 768, ff1_b, nullptr, ffhs, M, 768, 1024, 1);

    // 10. f = ffh @ ff2_w + ff2_b  (into 'offs' buffer)
    gemm_mma<<<dim3(2, gy), 256>>>(ffhs, 2048, 2048, wtf2, 3072, ff2_b, offs, nullptr, M, 3072, 256, 0);

    // 11. out = LN(x + f)
    add_ln_kernel<<<M, 256>>>(x, offs, ln2_g, ln2_b, outp, nullptr);
}

// round 4
// speedup vs baseline: 1.6884x; 1.0017x over previous
#include <cuda_runtime.h>
#include <cuda_bf16.h>
#include <cstdint>
#include <math.h>

// ---------------- problem constants ----------------
#define Bq    4
#define LIN   13294
#define MTOK  (Bq * LIN)      // 53176
#define DMODEL 256
#define NHEAD 8
#define NLVL  4
#define NPTS  4
#define DH    32
#define DFF   1024

// ---------------- scratch (device globals) ----------------
__device__ float g_q    [(size_t)MTOK * DMODEL];
__device__ __nv_bfloat16 g_qs [(size_t)MTOK * 2 * DMODEL];     // [hi|lo]
__device__ float g_value[(size_t)MTOK * DMODEL];
__device__ float g_offs [(size_t)MTOK * DMODEL];   // also reused for ff2 out
__device__ float g_aw   [(size_t)MTOK * 128];
__device__ __nv_bfloat16 g_msdas[(size_t)MTOK * 2 * DMODEL];
__device__ float g_src2 [(size_t)MTOK * DMODEL];
__device__ float g_x    [(size_t)MTOK * DMODEL];
__device__ __nv_bfloat16 g_xs [(size_t)MTOK * 2 * DMODEL];
__device__ __nv_bfloat16 g_ffhs[(size_t)MTOK * 2 * DFF];
// fused projection weight [640, 768] bf16: rows 0-255 value, 256-511 offs, 512-639 attn
__device__ __nv_bfloat16 g_wt_proj[640 * 768];
__device__ float g_bias_proj[640];
__device__ __nv_bfloat16 g_wt_out  [256 * 768];
__device__ __nv_bfloat16 g_wt_ff1  [1024 * 768];
__device__ __nv_bfloat16 g_wt_ff2  [256 * 3072];

// ---------------- helpers ----------------
__device__ __forceinline__ uint32_t smem_u32(const void* p) {
    uint32_t a;
    asm("{ .reg .u64 t; cvta.to.shared.u64 t, %1; cvt.u32.u64 %0, t; }" : "=r"(a) : "l"(p));
    return a;
}
#define CP_ASYNC16(dst, src) \
    asm volatile("cp.async.cg.shared.global [%0], [%1], 16;\n" :: "r"(dst), "l"(src) : "memory")
#define CP_COMMIT() asm volatile("cp.async.commit_group;\n" ::: "memory")
#define CP_WAIT(n)  asm volatile("cp.async.wait_group %0;\n" :: "n"(n) : "memory")

__device__ __forceinline__ void ldmatrix_x4(uint32_t& r0, uint32_t& r1, uint32_t& r2, uint32_t& r3, uint32_t addr) {
    asm volatile("ldmatrix.sync.aligned.m8n8.x4.shared.b16 {%0,%1,%2,%3}, [%4];"
                 : "=r"(r0), "=r"(r1), "=r"(r2), "=r"(r3) : "r"(addr));
}
__device__ __forceinline__ void mma_bf16(float* c, const uint32_t* a, const uint32_t* b) {
    asm volatile("mma.sync.aligned.m16n8k16.row.col.f32.bf16.bf16.f32 "
                 "{%0,%1,%2,%3}, {%4,%5,%6,%7}, {%8,%9}, {%0,%1,%2,%3};"
                 : "+f"(c[0]), "+f"(c[1]), "+f"(c[2]), "+f"(c[3])
                 : "r"(a[0]), "r"(a[1]), "r"(a[2]), "r"(a[3]), "r"(b[0]), "r"(b[1]));
}

// ---------------- bf16 warp-MMA GEMM, 4-stage cp.async pipeline ------------
// C = A_logical[M,Kfull] @ B[N,Kfull]^T + bias; A column remap: k<k2 ? k : k-k2.
// Tile 128x128, BK=32, 8 warps (4M x 2N).
// mode 0: Cf fp32 [M,N].  mode 1: Cs bf16 hi/lo split (stride 2N).
// mode 2: projection routing: cols 0-255 -> Cf (stride 256), 256-511 -> C2
//         (stride 256), 512-639 -> C3 (stride 128). bias indexed by global col.
#define PADS 40   // smem row stride in bf16
#define STAGE_ELEMS (128 * PADS)
#define NSTAGE 4
#define GEMM_SMEM (2 * NSTAGE * STAGE_ELEMS * 2)   // 81920 bytes

__global__ __launch_bounds__(256, 2)
void gemm_mma(const __nv_bfloat16* __restrict__ A, int lda, int k2,
              const __nv_bfloat16* __restrict__ B, int ldb,
              const float* __restrict__ bias,
              float* __restrict__ Cf, __nv_bfloat16* __restrict__ Cs,
              float* __restrict__ C2, float* __restrict__ C3,
              int M, int Kfull, int N, int relu, int mode)
{
    extern __shared__ __align__(16) __nv_bfloat16 dynsmem[];

    const int tid  = threadIdx.x;
    const int wid  = tid >> 5;
    const int lane = tid & 31;
    const int wm   = wid & 3;
    const int wn   = wid >> 2;
    const int row0 = blockIdx.y * 128;
    const int col0 = blockIdx.x * 128;

    const uint32_t sbase = smem_u32(dynsmem);
    const int NC = Kfull >> 5;   // BK = 32, assumes NC >= 3

    float acc[2][8][4];
#pragma unroll
    for (int i = 0; i < 2; i++)
#pragma unroll
        for (int j = 0; j < 8; j++)
#pragma unroll
            for (int t = 0; t < 4; t++) acc[i][j][t] = 0.f;

#define LOAD_STAGE(buf, cc) do {                                              \
        int _kc = (cc) << 5;                                                  \
        int _acol = (_kc < k2) ? _kc : _kc - k2;                              \
        uint32_t _dA = sbase + (buf) * (STAGE_ELEMS * 2);                     \
        uint32_t _dB = sbase + (NSTAGE + (buf)) * (STAGE_ELEMS * 2);          \
        _Pragma("unroll")                                                     \
        for (int _i = 0; _i < 2; ++_i) {                                      \
            int _c = tid + _i * 256;                                          \
            int _r = _c >> 2, _k8 = _c & 3;                                   \
            int _gr = row0 + _r; if (_gr >= M) _gr = M - 1;                   \
            CP_ASYNC16(_dA + (_r * PADS + _k8 * 8) * 2,                       \
                       A + (size_t)_gr * lda + _acol + _k8 * 8);              \
        }                                                                     \
        _Pragma("unroll")                                                     \
        for (int _i = 0; _i < 2; ++_i) {                                      \
            int _c = tid + _i * 256;                                          \
            int _r = _c >> 2, _k8 = _c & 3;                                   \
            CP_ASYNC16(_dB + (_r * PADS + _k8 * 8) * 2,                       \
                       B + (size_t)(col0 + _r) * ldb + _kc + _k8 * 8);        \
        }                                                                     \
    } while (0)

    // preload 3 stages
    LOAD_STAGE(0, 0); CP_COMMIT();
    LOAD_STAGE(1, 1); CP_COMMIT();
    LOAD_STAGE(2, 2); CP_COMMIT();

    for (int c = 0; c < NC; ++c) {
        const int buf = c & 3;
        CP_WAIT(2);
        __syncthreads();

        // issue prefetch for stage c+3 (always commit to keep group count fixed)
        if (c + 3 < NC) LOAD_STAGE((c + 3) & 3, c + 3);
        CP_COMMIT();

        const uint32_t baseA = sbase + buf * (STAGE_ELEMS * 2);
        const uint32_t baseB = sbase + (NSTAGE + buf) * (STAGE_ELEMS * 2);

#pragma unroll
        for (int kk = 0; kk < 32; kk += 16) {
            uint32_t a[2][4];
#pragma unroll
            for (int mt = 0; mt < 2; mt++) {
                int r = wm * 32 + mt * 16 + (lane & 15);
                int kc = kk + ((lane & 16) ? 8 : 0);
                ldmatrix_x4(a[mt][0], a[mt][1], a[mt][2], a[mt][3],
                            baseA + (r * PADS + kc) * 2);
            }
            uint32_t b[8][2];
#pragma unroll
            for (int np = 0; np < 4; np++) {
                int n = wn * 64 + np * 16 + (lane & 7) + ((lane & 16) ? 8 : 0);
                int kc = kk + ((lane & 8) ? 8 : 0);
                ldmatrix_x4(b[2 * np][0], b[2 * np][1], b[2 * np + 1][0], b[2 * np + 1][1],
                            baseB + (n * PADS + kc) * 2);
            }
#pragma unroll
            for (int mt = 0; mt < 2; mt++)
#pragma unroll
                for (int nt = 0; nt < 8; nt++)
                    mma_bf16(acc[mt][nt], a[mt], b[nt]);
        }
        __syncthreads();
    }

    // ---- epilogue ----
    // mode 2 routing decided per tile (each 128-col tile is inside one region)
    float* outp = Cf;
    int ostride = N, coff = 0;
    if (mode == 2) {
        if (col0 < 256)      { outp = Cf; ostride = 256; coff = 0; }
        else if (col0 < 512) { outp = C2; ostride = 256; coff = 256; }
        else                 { outp = C3; ostride = 128; coff = 512; }
    }

#pragma unroll
    for (int mt = 0; mt < 2; mt++) {
#pragma unroll
        for (int half = 0; half < 2; half++) {
            int r = row0 + wm * 32 + mt * 16 + (lane >> 2) + half * 8;
            if (r >= M) continue;
#pragma unroll
            for (int nt = 0; nt < 8; nt++) {
                int cidx = col0 + wn * 64 + nt * 8 + (lane & 3) * 2;
                float v0 = acc[mt][nt][half * 2 + 0] + bias[cidx];
                float v1 = acc[mt][nt][half * 2 + 1] + bias[cidx + 1];
                if (relu) { v0 = fmaxf(v0, 0.f); v1 = fmaxf(v1, 0.f); }
                if (mode == 1) {
                    __nv_bfloat16 h0 = __float2bfloat16(v0);
                    __nv_bfloat16 h1 = __float2bfloat16(v1);
                    __nv_bfloat16 l0 = __float2bfloat16(v0 - __bfloat162float(h0));
                    __nv_bfloat16 l1 = __float2bfloat16(v1 - __bfloat162float(h1));
                    __nv_bfloat162 hv; hv.x = h0; hv.y = h1;
                    __nv_bfloat162 lv; lv.x = l0; lv.y = l1;
                    *reinterpret_cast<__nv_bfloat162*>(Cs + (size_t)r * 2 * N + cidx) = hv;
                    *reinterpret_cast<__nv_bfloat162*>(Cs + (size_t)r * 2 * N + N + cidx) = lv;
                } else {
                    float2 o = make_float2(v0, v1);
                    *reinterpret_cast<float2*>(outp + (size_t)r * ostride + (cidx - coff)) = o;
                }
            }
        }
    }
#undef LOAD_STAGE
}

// ---------------- prep kernels ----------------
__global__ void add_split_kernel(const float* __restrict__ a, const float* __restrict__ b,
                                 float* __restrict__ q, __nv_bfloat16* __restrict__ qs, int n)
{
    int i = blockIdx.x * blockDim.x + threadIdx.x;
    if (i >= n) return;
    float v = a[i] + b[i];
    q[i] = v;
    int r = i >> 8, c = i & 255;
    __nv_bfloat16 h = __float2bfloat16(v);
    float lo = v - __bfloat162float(h);
    qs[(size_t)r * 512 + c] = h;
    qs[(size_t)r * 512 + 256 + c] = __float2bfloat16(lo);
}

// W [K,N] fp32 -> Wt [N, 3K] bf16: [hi | hi | lo]
__global__ void wsplit_kernel(const float* __restrict__ W, __nv_bfloat16* __restrict__ Wt, int K_, int N_)
{
    int i = blockIdx.x * blockDim.x + threadIdx.x;
    if (i >= K_ * N_) return;
    int k = i / N_, n = i % N_;
    float v = W[i];
    __nv_bfloat16 h = __float2bfloat16(v);
    float lo = v - __bfloat162float(h);
    size_t b = (size_t)n * 3 * K_;
    Wt[b + k] = h;
    Wt[b + K_ + k] = h;
    Wt[b + 2 * K_ + k] = __float2bfloat16(lo);
}

__global__ void bias_concat_kernel(const float* __restrict__ vb, const float* __restrict__ ob,
                                   const float* __restrict__ ab, float* __restrict__ dst)
{
    int i = threadIdx.x + blockIdx.x * blockDim.x;
    if (i < 256) dst[i] = vb[i];
    else if (i < 512) dst[i] = ob[i - 256];
    else if (i < 640) dst[i] = ab[i - 512];
}

// ---------------- softmax over 16 contiguous logits ----------------
__global__ void softmax16_kernel(float* __restrict__ aw, int total)
{
    int i = blockIdx.x * blockDim.x + threadIdx.x;
    if (i >= total) return;
    float* p = aw + (size_t)i * 16;
    float v[16];
    float m = -1e30f;
#pragma unroll
    for (int j = 0; j < 16; j++) { v[j] = p[j]; m = fmaxf(m, v[j]); }
    float s = 0.f;
#pragma unroll
    for (int j = 0; j < 16; j++) { v[j] = expf(v[j] - m); s += v[j]; }
    float inv = 1.f / s;
#pragma unroll
    for (int j = 0; j < 16; j++) p[j] = v[j] * inv;
}

// ---------------- MSDA bilinear sampling (writes bf16 hi/lo split) ---------
__global__ __launch_bounds__(256)
void msda_kernel(const float* __restrict__ value, const float* __restrict__ offs,
                 const float* __restrict__ aw, const float* __restrict__ ref,
                 const int* __restrict__ shapes, const int* __restrict__ starts,
                 __nv_bfloat16* __restrict__ outs)
{
    const int tok = blockIdx.x;
    const int h = threadIdx.x >> 5;
    const int lane = threadIdx.x & 31;
    const int b = tok / LIN;

    const float* refp = ref + (size_t)tok * (NLVL * 2);
    float acc = 0.f;

#pragma unroll
    for (int l = 0; l < NLVL; l++) {
        const int Hl = shapes[l * 2 + 0];
        const int Wl = shapes[l * 2 + 1];
        const int s  = starts[l];
        const float fW = (float)Wl, fH = (float)Hl;
        const float rx = refp[l * 2 + 0];
        const float ry = refp[l * 2 + 1];

        const float* op = offs + (size_t)tok * 256 + (size_t)((h * NLVL + l) * NPTS) * 2;
        const float* ap = aw + (size_t)tok * 128 + h * 16 + l * NPTS;
        const size_t vbase = ((size_t)b * LIN + s) * DMODEL + h * DH + lane;

#pragma unroll
        for (int p = 0; p < NPTS; p++) {
            float ox = op[p * 2 + 0];
            float oy = op[p * 2 + 1];
            float a  = ap[p];
            float x = (rx + ox / fW) * fW - 0.5f;
            float y = (ry + oy / fH) * fH - 0.5f;
            float x0f = floorf(x), y0f = floorf(y);
            float dx = x - x0f, dy = y - y0f;
            int x0 = (int)x0f, y0 = (int)y0f;

            float w00 = (1.f - dx) * (1.f - dy);
            float w10 = dx * (1.f - dy);
            float w01 = (1.f - dx) * dy;
            float w11 = dx * dy;

            bool xv0 = (x0 >= 0) && (x0 < Wl);
            bool xv1 = (x0 + 1 >= 0) && (x0 + 1 < Wl);
            bool yv0 = (y0 >= 0) && (y0 < Hl);
            bool yv1 = (y0 + 1 >= 0) && (y0 + 1 < Hl);

            float v00 = 0.f, v10 = 0.f, v01 = 0.f, v11 = 0.f;
            if (yv0 && xv0) v00 = value[vbase + (size_t)(y0 * Wl + x0) * DMODEL];
            if (yv0 && xv1) v10 = value[vbase + (size_t)(y0 * Wl + x0 + 1) * DMODEL];
            if (yv1 && xv0) v01 = value[vbase + (size_t)((y0 + 1) * Wl + x0) * DMODEL];
            if (yv1 && xv1) v11 = value[vbase + (size_t)((y0 + 1) * Wl + x0 + 1) * DMODEL];

            acc = fmaf(a, w00 * v00 + w10 * v10 + w01 * v01 + w11 * v11, acc);
        }
    }
    int ch = h * DH + lane;
    __nv_bfloat16 hh = __float2bfloat16(acc);
    outs[(size_t)tok * 512 + ch] = hh;
    outs[(size_t)tok * 512 + 256 + ch] = __float2bfloat16(acc - __bfloat162float(hh));
}

// ---------------- fused residual add + LayerNorm (+ optional split) --------
__global__ __launch_bounds__(256)
void add_ln_kernel(const float* __restrict__ a, const float* __restrict__ r,
                   const float* __restrict__ g, const float* __restrict__ bb,
                   float* __restrict__ out, __nv_bfloat16* __restrict__ outs)
{
    const int tok = blockIdx.x;
    const int i = threadIdx.x;
    float v = a[(size_t)tok * DMODEL + i] + r[(size_t)tok * DMODEL + i];

    __shared__ float sh[8];
    float s = v;
#pragma unroll
    for (int o = 16; o; o >>= 1) s += __shfl_xor_sync(0xffffffffu, s, o);
    if ((i & 31) == 0) sh[i >> 5] = s;
    __syncthreads();
    float tot = 0.f;
#pragma unroll
    for (int w = 0; w < 8; w++) tot += sh[w];
    float mean = tot * (1.f / 256.f);
    __syncthreads();

    float d = v - mean;
    float s2 = d * d;
#pragma unroll
    for (int o = 16; o; o >>= 1) s2 += __shfl_xor_sync(0xffffffffu, s2, o);
    if ((i & 31) == 0) sh[i >> 5] = s2;
    __syncthreads();
    float tot2 = 0.f;
#pragma unroll
    for (int w = 0; w < 8; w++) tot2 += sh[w];
    float var = tot2 * (1.f / 256.f);

    float o = d * rsqrtf(var + 1e-5f) * g[i] + bb[i];
    out[(size_t)tok * DMODEL + i] = o;
    if (outs) {
        __nv_bfloat16 h = __float2bfloat16(o);
        outs[(size_t)tok * 512 + i] = h;
        outs[(size_t)tok * 512 + 256 + i] = __float2bfloat16(o - __bfloat162float(h));
    }
}

// ---------------- launch ----------------
extern "C" void kernel_launch(void* const* d_in, const int* in_sizes, int n_in,
                              void* d_out, int out_size)
{
    const float* src    = (const float*)d_in[0];
    const float* pos    = (const float*)d_in[1];
    const float* refpts = (const float*)d_in[2];
    const int*   shapes = (const int*)  d_in[3];
    const int*   starts = (const int*)  d_in[4];
    const float* value_w = (const float*)d_in[5];
    const float* value_b = (const float*)d_in[6];
    const float* offs_w  = (const float*)d_in[7];
    const float* offs_b  = (const float*)d_in[8];
    const float* attn_w  = (const float*)d_in[9];
    const float* attn_b  = (const float*)d_in[10];
    const float* out_w   = (const float*)d_in[11];
    const float* out_b   = (const float*)d_in[12];
    const float* ln1_g   = (const float*)d_in[13];
    const float* ln1_b   = (const float*)d_in[14];
    const float* ff1_w   = (const float*)d_in[15];
    const float* ff1_b   = (const float*)d_in[16];
    const float* ff2_w   = (const float*)d_in[17];
    const float* ff2_b   = (const float*)d_in[18];
    const float* ln2_g   = (const float*)d_in[19];
    const float* ln2_b   = (const float*)d_in[20];
    float* outp = (float*)d_out;

    float *q, *value, *offs, *aw, *src2, *x, *biasp;
    __nv_bfloat16 *qs, *msdas, *xs, *ffhs;
    __nv_bfloat16 *wtp, *wtu, *wtf1, *wtf2;
    cudaGetSymbolAddress((void**)&q,     g_q);
    cudaGetSymbolAddress((void**)&qs,    g_qs);
    cudaGetSymbolAddress((void**)&value, g_value);
    cudaGetSymbolAddress((void**)&offs,  g_offs);
    cudaGetSymbolAddress((void**)&aw,    g_aw);
    cudaGetSymbolAddress((void**)&msdas, g_msdas);
    cudaGetSymbolAddress((void**)&src2,  g_src2);
    cudaGetSymbolAddress((void**)&x,     g_x);
    cudaGetSymbolAddress((void**)&xs,    g_xs);
    cudaGetSymbolAddress((void**)&ffhs,  g_ffhs);
    cudaGetSymbolAddress((void**)&wtp,   g_wt_proj);
    cudaGetSymbolAddress((void**)&wtu,   g_wt_out);
    cudaGetSymbolAddress((void**)&wtf1,  g_wt_ff1);
    cudaGetSymbolAddress((void**)&wtf2,  g_wt_ff2);
    cudaGetSymbolAddress((void**)&biasp, g_bias_proj);

    cudaFuncSetAttribute(gemm_mma, cudaFuncAttributeMaxDynamicSharedMemorySize, GEMM_SMEM);

    const int M = MTOK;
    const int gy = (M + 127) / 128;

    // weight prep: fused proj weight [640, 768]
    wsplit_kernel<<<(256 * 256 + 255) / 256, 256>>>(value_w, wtp, 256, 256);
    wsplit_kernel<<<(256 * 256 + 255) / 256, 256>>>(offs_w,  wtp + 256 * 768, 256, 256);
    wsplit_kernel<<<(256 * 128 + 255) / 256, 256>>>(attn_w,  wtp + 512 * 768, 256, 128);
    wsplit_kernel<<<(256 * 256 + 255) / 256, 256>>>(out_w,   wtu, 256, 256);
    wsplit_kernel<<<(256 * 1024 + 255) / 256, 256>>>(ff1_w,  wtf1, 256, 1024);
    wsplit_kernel<<<(1024 * 256 + 255) / 256, 256>>>(ff2_w,  wtf2, 1024, 256);
    bias_concat_kernel<<<3, 256>>>(value_b, offs_b, attn_b, biasp);

    // 1. q = src + pos (+ bf16 split)
    add_split_kernel<<<(M * DMODEL + 255) / 256, 256>>>(src, pos, q, qs, M * DMODEL);

    // 2. fused projections: [value | offs | aw] = qs @ wt_proj^T
    gemm_mma<<<dim3(5, gy), 256, GEMM_SMEM>>>(qs, 512, 512, wtp, 768, biasp,
                                              value, nullptr, offs, aw, M, 768, 640, 0, 2);

    // 3. softmax
    softmax16_kernel<<<(M * NHEAD + 255) / 256, 256>>>(aw, M * NHEAD);

    // 4. deformable sampling -> bf16 split directly
    msda_kernel<<<M, 256>>>(value, offs, aw, refpts, shapes, starts, msdas);

    // 5. output projection: src2 = msda @ out_w + out_b
    gemm_mma<<<dim3(2, gy), 256, GEMM_SMEM>>>(msdas, 512, 512, wtu, 768, out_b,
                                              src2, nullptr, nullptr, nullptr, M, 768, 256, 0, 0);

    // 6. x = LN(q + src2)  (+ split xs)
    add_ln_kernel<<<M, 256>>>(q, src2, ln1_g, ln1_b, x, xs);

    // 7. ffh = relu(x @ ff1_w + ff1_b) -> split only
    gemm_mma<<<dim3(8, gy), 256, GEMM_SMEM>>>(xs, 512, 512, wtf1, 768, ff1_b,
                                              nullptr, ffhs, nullptr, nullptr, M, 768, 1024, 1, 1);

    // 8. f = ffh @ ff2_w + ff2_b  (into 'offs' buffer)
    gemm_mma<<<dim3(2, gy), 256, GEMM_SMEM>>>(ffhs, 2048, 2048, wtf2, 3072, ff2_b,
                                              offs, nullptr, nullptr, nullptr, M, 3072, 256, 0, 0);

    // 9. out = LN(x + f)
    add_ln_kernel<<<M, 256>>>(x, offs, ln2_g, ln2_b, outp, nullptr);
}

// round 5
// speedup vs baseline: 2.0584x; 1.2191x over previous
#include <cuda_runtime.h>
#include <cuda_fp16.h>
#include <cstdint>
#include <math.h>

// ---------------- problem constants ----------------
#define Bq    4
#define LIN   13294
#define MTOK  (Bq * LIN)      // 53176
#define DMODEL 256
#define NHEAD 8
#define NLVL  4
#define NPTS  4
#define DH    32
#define DFF   1024

// ---------------- scratch (device globals) ----------------
__device__ float  g_q    [(size_t)MTOK * DMODEL];
__device__ __half g_qh   [(size_t)MTOK * DMODEL];
__device__ __half g_value[(size_t)MTOK * DMODEL];
__device__ float  g_offs [(size_t)MTOK * DMODEL];   // reused for ff2 out
__device__ float  g_aw   [(size_t)MTOK * 128];
__device__ __half g_msdah[(size_t)MTOK * DMODEL];
__device__ float  g_src2 [(size_t)MTOK * DMODEL];
__device__ float  g_x    [(size_t)MTOK * DMODEL];
__device__ __half g_xh   [(size_t)MTOK * DMODEL];
__device__ __half g_ffh  [(size_t)MTOK * DFF];
// weights: Wt[N, 2K] fp16 K-major: [hi | lo]
__device__ __half g_wt_proj[640 * 512];    // rows: 0-255 value, 256-511 offs, 512-639 attn
__device__ __half g_wt_out [256 * 512];
__device__ __half g_wt_ff1 [1024 * 512];
__device__ __half g_wt_ff2 [256 * 2048];
__device__ float  g_bias_proj[640];

// ---------------- helpers ----------------
__device__ __forceinline__ uint32_t smem_u32(const void* p) {
    uint32_t a;
    asm("{ .reg .u64 t; cvta.to.shared.u64 t, %1; cvt.u32.u64 %0, t; }" : "=r"(a) : "l"(p));
    return a;
}
#define CP_ASYNC16(dst, src) \
    asm volatile("cp.async.cg.shared.global [%0], [%1], 16;\n" :: "r"(dst), "l"(src) : "memory")
#define CP_COMMIT() asm volatile("cp.async.commit_group;\n" ::: "memory")
#define CP_WAIT(n)  asm volatile("cp.async.wait_group %0;\n" :: "n"(n) : "memory")

__device__ __forceinline__ void ldmatrix_x4(uint32_t& r0, uint32_t& r1, uint32_t& r2, uint32_t& r3, uint32_t addr) {
    asm volatile("ldmatrix.sync.aligned.m8n8.x4.shared.b16 {%0,%1,%2,%3}, [%4];"
                 : "=r"(r0), "=r"(r1), "=r"(r2), "=r"(r3) : "r"(addr));
}
__device__ __forceinline__ void mma_f16(float* c, const uint32_t* a, const uint32_t* b) {
    asm volatile("mma.sync.aligned.m16n8k16.row.col.f32.f16.f16.f32 "
                 "{%0,%1,%2,%3}, {%4,%5,%6,%7}, {%8,%9}, {%0,%1,%2,%3};"
                 : "+f"(c[0]), "+f"(c[1]), "+f"(c[2]), "+f"(c[3])
                 : "r"(a[0]), "r"(a[1]), "r"(a[2]), "r"(a[3]), "r"(b[0]), "r"(b[1]));
}

// ---------------- fp16 warp-MMA GEMM, 4-stage cp.async pipeline ------------
// C = A_logical[M,Kfull] @ B[N,Kfull]^T + bias.
// A physical [M, lda] fp16; logical col k maps to (k < k2 ? k : k - k2)
//   -> with k2 = K the A data is consumed twice (against W hi then W lo).
// B [N, Kfull] fp16 = [W_hi | W_lo].
// Tile 128x128, BK=32, 8 warps (4M x 2N).
// mode 0: Cf fp32 [M,N]. mode 1: Ch fp16 [M,N].
// mode 2: cols 0-255 -> Ch (value fp16, stride 256); 256-511 -> C2 (fp32, 256);
//         512-639 -> C3 (fp32, 128). bias indexed by global col.
#define PADS 40
#define STAGE_ELEMS (128 * PADS)
#define NSTAGE 4
#define GEMM_SMEM (2 * NSTAGE * STAGE_ELEMS * 2)   // 81920 bytes

__global__ __launch_bounds__(256, 2)
void gemm_mma(const __half* __restrict__ A, int lda, int k2,
              const __half* __restrict__ B, int ldb,
              const float* __restrict__ bias,
              float* __restrict__ Cf, __half* __restrict__ Ch,
              float* __restrict__ C2, float* __restrict__ C3,
              int M, int Kfull, int N, int relu, int mode)
{
    extern __shared__ __align__(16) __half dynsmem[];

    const int tid  = threadIdx.x;
    const int wid  = tid >> 5;
    const int lane = tid & 31;
    const int wm   = wid & 3;
    const int wn   = wid >> 2;
    const int row0 = blockIdx.y * 128;
    const int col0 = blockIdx.x * 128;

    const uint32_t sbase = smem_u32(dynsmem);
    const int NC = Kfull >> 5;

    float acc[2][8][4];
#pragma unroll
    for (int i = 0; i < 2; i++)
#pragma unroll
        for (int j = 0; j < 8; j++)
#pragma unroll
            for (int t = 0; t < 4; t++) acc[i][j][t] = 0.f;

#define LOAD_STAGE(buf, cc) do {                                              \
        int _kc = (cc) << 5;                                                  \
        int _acol = (_kc < k2) ? _kc : _kc - k2;                              \
        uint32_t _dA = sbase + (buf) * (STAGE_ELEMS * 2);                     \
        uint32_t _dB = sbase + (NSTAGE + (buf)) * (STAGE_ELEMS * 2);          \
        _Pragma("unroll")                                                     \
        for (int _i = 0; _i < 2; ++_i) {                                      \
            int _c = tid + _i * 256;                                          \
            int _r = _c >> 2, _k8 = _c & 3;                                   \
            int _gr = row0 + _r; if (_gr >= M) _gr = M - 1;                   \
            CP_ASYNC16(_dA + (_r * PADS + _k8 * 8) * 2,                       \
                       A + (size_t)_gr * lda + _acol + _k8 * 8);              \
        }                                                                     \
        _Pragma("unroll")                                                     \
        for (int _i = 0; _i < 2; ++_i) {                                      \
            int _c = tid + _i * 256;                                          \
            int _r = _c >> 2, _k8 = _c & 3;                                   \
            CP_ASYNC16(_dB + (_r * PADS + _k8 * 8) * 2,                       \
                       B + (size_t)(col0 + _r) * ldb + _kc + _k8 * 8);        \
        }                                                                     \
    } while (0)

    LOAD_STAGE(0, 0); CP_COMMIT();
    LOAD_STAGE(1, 1); CP_COMMIT();
    LOAD_STAGE(2, 2); CP_COMMIT();

    for (int c = 0; c < NC; ++c) {
        const int buf = c & 3;
        CP_WAIT(2);
        __syncthreads();

        if (c + 3 < NC) LOAD_STAGE((c + 3) & 3, c + 3);
        CP_COMMIT();

        const uint32_t baseA = sbase + buf * (STAGE_ELEMS * 2);
        const uint32_t baseB = sbase + (NSTAGE + buf) * (STAGE_ELEMS * 2);

#pragma unroll
        for (int kk = 0; kk < 32; kk += 16) {
            uint32_t a[2][4];
#pragma unroll
            for (int mt = 0; mt < 2; mt++) {
                int r = wm * 32 + mt * 16 + (lane & 15);
                int kc = kk + ((lane & 16) ? 8 : 0);
                ldmatrix_x4(a[mt][0], a[mt][1], a[mt][2], a[mt][3],
                            baseA + (r * PADS + kc) * 2);
            }
            uint32_t b[8][2];
#pragma unroll
            for (int np = 0; np < 4; np++) {
                int n = wn * 64 + np * 16 + (lane & 7) + ((lane & 16) ? 8 : 0);
                int kc = kk + ((lane & 8) ? 8 : 0);
                ldmatrix_x4(b[2 * np][0], b[2 * np][1], b[2 * np + 1][0], b[2 * np + 1][1],
                            baseB + (n * PADS + kc) * 2);
            }
#pragma unroll
            for (int mt = 0; mt < 2; mt++)
#pragma unroll
                for (int nt = 0; nt < 8; nt++)
                    mma_f16(acc[mt][nt], a[mt], b[nt]);
        }
        __syncthreads();
    }

    // ---- epilogue ----
    float* outf = Cf;
    __half* outh = Ch;
    int ostride = N, coff = 0;
    int write_half = (mode == 1);
    if (mode == 2) {
        if (col0 < 256)      { outh = Ch; ostride = 256; coff = 0; write_half = 1; }
        else if (col0 < 512) { outf = C2; ostride = 256; coff = 256; }
        else                 { outf = C3; ostride = 128; coff = 512; }
    }

#pragma unroll
    for (int mt = 0; mt < 2; mt++) {
#pragma unroll
        for (int half_i = 0; half_i < 2; half_i++) {
            int r = row0 + wm * 32 + mt * 16 + (lane >> 2) + half_i * 8;
            if (r >= M) continue;
#pragma unroll
            for (int nt = 0; nt < 8; nt++) {
                int cidx = col0 + wn * 64 + nt * 8 + (lane & 3) * 2;
                float v0 = acc[mt][nt][half_i * 2 + 0] + bias[cidx];
                float v1 = acc[mt][nt][half_i * 2 + 1] + bias[cidx + 1];
                if (relu) { v0 = fmaxf(v0, 0.f); v1 = fmaxf(v1, 0.f); }
                if (write_half) {
                    __half2 hv;
                    hv.x = __float2half_rn(v0);
                    hv.y = __float2half_rn(v1);
                    *reinterpret_cast<__half2*>(outh + (size_t)r * ostride + (cidx - coff)) = hv;
                } else {
                    float2 o = make_float2(v0, v1);
                    *reinterpret_cast<float2*>(outf + (size_t)r * ostride + (cidx - coff)) = o;
                }
            }
        }
    }
#undef LOAD_STAGE
}

// ---------------- combined weight prep (single launch) ----------------
// W [K,N] fp32 -> Wt [N, 2K] fp16: [hi | lo]; plus bias concat.
__device__ __forceinline__ void wsplit1(const float* __restrict__ W, __half* __restrict__ Wt,
                                        int K_, int N_, int i)
{
    int k = i / N_, n = i % N_;
    float v = W[i];
    __half h = __float2half_rn(v);
    __half l = __float2half_rn(v - __half2float(h));
    Wt[(size_t)n * 2 * K_ + k] = h;
    Wt[(size_t)n * 2 * K_ + K_ + k] = l;
}

__global__ void prep_kernel(const float* __restrict__ vW, const float* __restrict__ oW,
                            const float* __restrict__ aW, const float* __restrict__ uW,
                            const float* __restrict__ f1W, const float* __restrict__ f2W,
                            const float* __restrict__ vb, const float* __restrict__ ob,
                            const float* __restrict__ ab,
                            __half* __restrict__ wtp, __half* __restrict__ wtu,
                            __half* __restrict__ wtf1, __half* __restrict__ wtf2,
                            float* __restrict__ biasp)
{
    int i = blockIdx.x * blockDim.x + threadIdx.x;
    if (i < 65536)       { wsplit1(vW, wtp, 256, 256, i); return; }
    i -= 65536;
    if (i < 65536)       { wsplit1(oW, wtp + 256 * 512, 256, 256, i); return; }
    i -= 65536;
    if (i < 32768)       { wsplit1(aW, wtp + 512 * 512, 256, 128, i); return; }
    i -= 32768;
    if (i < 65536)       { wsplit1(uW, wtu, 256, 256, i); return; }
    i -= 65536;
    if (i < 262144)      { wsplit1(f1W, wtf1, 256, 1024, i); return; }
    i -= 262144;
    if (i < 262144)      { wsplit1(f2W, wtf2, 1024, 256, i); return; }
    i -= 262144;
    if (i < 256)         { biasp[i] = vb[i]; return; }
    if (i < 512)         { biasp[i] = ob[i - 256]; return; }
    if (i < 640)         { biasp[i] = ab[i - 512]; return; }
}

// ---------------- q = src + pos (fp32 + fp16) ----------------
__global__ void add_split_kernel(const float* __restrict__ a, const float* __restrict__ b,
                                 float* __restrict__ q, __half* __restrict__ qh, int n)
{
    int i = blockIdx.x * blockDim.x + threadIdx.x;
    if (i >= n) return;
    float v = a[i] + b[i];
    q[i] = v;
    qh[i] = __float2half_rn(v);
}

// ---------------- softmax over 16 contiguous logits ----------------
__global__ void softmax16_kernel(float* __restrict__ aw, int total)
{
    int i = blockIdx.x * blockDim.x + threadIdx.x;
    if (i >= total) return;
    float* p = aw + (size_t)i * 16;
    float v[16];
    float m = -1e30f;
#pragma unroll
    for (int j = 0; j < 16; j++) { v[j] = p[j]; m = fmaxf(m, v[j]); }
    float s = 0.f;
#pragma unroll
    for (int j = 0; j < 16; j++) { v[j] = expf(v[j] - m); s += v[j]; }
    float inv = 1.f / s;
#pragma unroll
    for (int j = 0; j < 16; j++) p[j] = v[j] * inv;
}

// ---------------- MSDA bilinear sampling (fp16 value, fp16 out) ------------
__global__ __launch_bounds__(256)
void msda_kernel(const __half* __restrict__ value, const float* __restrict__ offs,
                 const float* __restrict__ aw, const float* __restrict__ ref,
                 const int* __restrict__ shapes, const int* __restrict__ starts,
                 __half* __restrict__ outh)
{
    const int tok = blockIdx.x;
    const int h = threadIdx.x >> 5;
    const int lane = threadIdx.x & 31;
    const int b = tok / LIN;

    const float* refp = ref + (size_t)tok * (NLVL * 2);
    float acc = 0.f;

#pragma unroll
    for (int l = 0; l < NLVL; l++) {
        const int Hl = shapes[l * 2 + 0];
        const int Wl = shapes[l * 2 + 1];
        const int s  = starts[l];
        const float fW = (float)Wl, fH = (float)Hl;
        const float rx = refp[l * 2 + 0];
        const float ry = refp[l * 2 + 1];

        const float* op = offs + (size_t)tok * 256 + (size_t)((h * NLVL + l) * NPTS) * 2;
        const float* ap = aw + (size_t)tok * 128 + h * 16 + l * NPTS;
        const size_t vbase = ((size_t)b * LIN + s) * DMODEL + h * DH + lane;

#pragma unroll
        for (int p = 0; p < NPTS; p++) {
            float ox = op[p * 2 + 0];
            float oy = op[p * 2 + 1];
            float a  = ap[p];
            float x = (rx + ox / fW) * fW - 0.5f;
            float y = (ry + oy / fH) * fH - 0.5f;
            float x0f = floorf(x), y0f = floorf(y);
            float dx = x - x0f, dy = y - y0f;
            int x0 = (int)x0f, y0 = (int)y0f;

            float w00 = (1.f - dx) * (1.f - dy);
            float w10 = dx * (1.f - dy);
            float w01 = (1.f - dx) * dy;
            float w11 = dx * dy;

            bool xv0 = (x0 >= 0) && (x0 < Wl);
            bool xv1 = (x0 + 1 >= 0) && (x0 + 1 < Wl);
            bool yv0 = (y0 >= 0) && (y0 < Hl);
            bool yv1 = (y0 + 1 >= 0) && (y0 + 1 < Hl);

            float v00 = 0.f, v10 = 0.f, v01 = 0.f, v11 = 0.f;
            if (yv0 && xv0) v00 = __half2float(value[vbase + (size_t)(y0 * Wl + x0) * DMODEL]);
            if (yv0 && xv1) v10 = __half2float(value[vbase + (size_t)(y0 * Wl + x0 + 1) * DMODEL]);
            if (yv1 && xv0) v01 = __half2float(value[vbase + (size_t)((y0 + 1) * Wl + x0) * DMODEL]);
            if (yv1 && xv1) v11 = __half2float(value[vbase + (size_t)((y0 + 1) * Wl + x0 + 1) * DMODEL]);

            acc = fmaf(a, w00 * v00 + w10 * v10 + w01 * v01 + w11 * v11, acc);
        }
    }
    outh[(size_t)tok * DMODEL + h * DH + lane] = __float2half_rn(acc);
}

// ---------------- fused residual add + LayerNorm (+ optional fp16 copy) ----
__global__ __launch_bounds__(256)
void add_ln_kernel(const float* __restrict__ a, const float* __restrict__ r,
                   const float* __restrict__ g, const float* __restrict__ bb,
                   float* __restrict__ out, __half* __restrict__ outh)
{
    const int tok = blockIdx.x;
    const int i = threadIdx.x;
    float v = a[(size_t)tok * DMODEL + i] + r[(size_t)tok * DMODEL + i];

    __shared__ float sh[8];
    float s = v;
#pragma unroll
    for (int o = 16; o; o >>= 1) s += __shfl_xor_sync(0xffffffffu, s, o);
    if ((i & 31) == 0) sh[i >> 5] = s;
    __syncthreads();
    float tot = 0.f;
#pragma unroll
    for (int w = 0; w < 8; w++) tot += sh[w];
    float mean = tot * (1.f / 256.f);
    __syncthreads();

    float d = v - mean;
    float s2 = d * d;
#pragma unroll
    for (int o = 16; o; o >>= 1) s2 += __shfl_xor_sync(0xffffffffu, s2, o);
    if ((i & 31) == 0) sh[i >> 5] = s2;
    __syncthreads();
    float tot2 = 0.f;
#pragma unroll
    for (int w = 0; w < 8; w++) tot2 += sh[w];
    float var = tot2 * (1.f / 256.f);

    float o = d * rsqrtf(var + 1e-5f) * g[i] + bb[i];
    out[(size_t)tok * DMODEL + i] = o;
    if (outh) outh[(size_t)tok * DMODEL + i] = __float2half_rn(o);
}

// ---------------- launch ----------------
extern "C" void kernel_launch(void* const* d_in, const int* in_sizes, int n_in,
                              void* d_out, int out_size)
{
    const float* src    = (const float*)d_in[0];
    const float* pos    = (const float*)d_in[1];
    const float* refpts = (const float*)d_in[2];
    const int*   shapes = (const int*)  d_in[3];
    const int*   starts = (const int*)  d_in[4];
    const float* value_w = (const float*)d_in[5];
    const float* value_b = (const float*)d_in[6];
    const float* offs_w  = (const float*)d_in[7];
    const float* offs_b  = (const float*)d_in[8];
    const float* attn_w  = (const float*)d_in[9];
    const float* attn_b  = (const float*)d_in[10];
    const float* out_w   = (const float*)d_in[11];
    const float* out_b   = (const float*)d_in[12];
    const float* ln1_g   = (const float*)d_in[13];
    const float* ln1_b   = (const float*)d_in[14];
    const float* ff1_w   = (const float*)d_in[15];
    const float* ff1_b   = (const float*)d_in[16];
    const float* ff2_w   = (const float*)d_in[17];
    const float* ff2_b   = (const float*)d_in[18];
    const float* ln2_g   = (const float*)d_in[19];
    const float* ln2_b   = (const float*)d_in[20];
    float* outp = (float*)d_out;

    float *q, *offs, *aw, *src2, *x, *biasp;
    __half *qh, *value, *msdah, *xh, *ffh;
    __half *wtp, *wtu, *wtf1, *wtf2;
    cudaGetSymbolAddress((void**)&q,     g_q);
    cudaGetSymbolAddress((void**)&qh,    g_qh);
    cudaGetSymbolAddress((void**)&value, g_value);
    cudaGetSymbolAddress((void**)&offs,  g_offs);
    cudaGetSymbolAddress((void**)&aw,    g_aw);
    cudaGetSymbolAddress((void**)&msdah, g_msdah);
    cudaGetSymbolAddress((void**)&src2,  g_src2);
    cudaGetSymbolAddress((void**)&x,     g_x);
    cudaGetSymbolAddress((void**)&xh,    g_xh);
    cudaGetSymbolAddress((void**)&ffh,   g_ffh);
    cudaGetSymbolAddress((void**)&wtp,   g_wt_proj);
    cudaGetSymbolAddress((void**)&wtu,   g_wt_out);
    cudaGetSymbolAddress((void**)&wtf1,  g_wt_ff1);
    cudaGetSymbolAddress((void**)&wtf2,  g_wt_ff2);
    cudaGetSymbolAddress((void**)&biasp, g_bias_proj);

    cudaFuncSetAttribute(gemm_mma, cudaFuncAttributeMaxDynamicSharedMemorySize, GEMM_SMEM);

    const int M = MTOK;
    const int gy = (M + 127) / 128;

    // 0. all weight prep in one launch
    prep_kernel<<<(754304 + 255) / 256, 256>>>(value_w, offs_w, attn_w, out_w, ff1_w, ff2_w,
                                               value_b, offs_b, attn_b,
                                               wtp, wtu, wtf1, wtf2, biasp);

    // 1. q = src + pos
    add_split_kernel<<<(M * DMODEL + 255) / 256, 256>>>(src, pos, q, qh, M * DMODEL);

    // 2. fused projections: [value(fp16) | offs | aw] = q @ [Wh|Wl]^T
    gemm_mma<<<dim3(5, gy), 256, GEMM_SMEM>>>(qh, 256, 256, wtp, 512, biasp,
                                              nullptr, value, offs, aw, M, 512, 640, 0, 2);

    // 3. softmax
    softmax16_kernel<<<(M * NHEAD + 255) / 256, 256>>>(aw, M * NHEAD);

    // 4. deformable sampling (fp16 value -> fp16 msda)
    msda_kernel<<<M, 256>>>(value, offs, aw, refpts, shapes, starts, msdah);

    // 5. output projection: src2 = msda @ out_w + out_b   <-- ncu -s 5 lands here
    gemm_mma<<<dim3(2, gy), 256, GEMM_SMEM>>>(msdah, 256, 256, wtu, 512, out_b,
                                              src2, nullptr, nullptr, nullptr, M, 512, 256, 0, 0);

    // 6. x = LN(q + src2)  (+ fp16 copy)
    add_ln_kernel<<<M, 256>>>(q, src2, ln1_g, ln1_b, x, xh);

    // 7. ffh = relu(x @ ff1_w + ff1_b) -> fp16
    gemm_mma<<<dim3(8, gy), 256, GEMM_SMEM>>>(xh, 256, 256, wtf1, 512, ff1_b,
                                              nullptr, ffh, nullptr, nullptr, M, 512, 1024, 1, 1);

    // 8. f = ffh @ ff2_w + ff2_b  (into 'offs' buffer)
    gemm_mma<<<dim3(2, gy), 256, GEMM_SMEM>>>(ffh, 1024, 1024, wtf2, 2048, ff2_b,
                                              offs, nullptr, nullptr, nullptr, M, 2048, 256, 0, 0);

    // 9. out = LN(x + f)
    add_ln_kernel<<<M, 256>>>(x, offs, ln2_g, ln2_b, outp, nullptr);
}

// round 6
// speedup vs baseline: 2.5041x; 1.2165x over previous
#include <cuda_runtime.h>
#include <cuda_fp16.h>
#include <cstdint>
#include <math.h>

// ---------------- problem constants ----------------
#define Bq    4
#define LIN   13294
#define MTOK  (Bq * LIN)      // 53176
#define DMODEL 256
#define NHEAD 8
#define NLVL  4
#define NPTS  4
#define DH    32
#define DFF   1024

// ---------------- scratch (device globals) ----------------
__device__ float  g_q    [(size_t)MTOK * DMODEL];
__device__ __half g_qh   [(size_t)MTOK * DMODEL];
__device__ __half g_value[(size_t)MTOK * DMODEL];
__device__ float  g_offs [(size_t)MTOK * DMODEL];   // reused for ff2 out
__device__ float  g_aw   [(size_t)MTOK * 128];      // raw logits
__device__ __half g_msdah[(size_t)MTOK * DMODEL];
__device__ float  g_src2 [(size_t)MTOK * DMODEL];
__device__ float  g_x    [(size_t)MTOK * DMODEL];
__device__ __half g_xh   [(size_t)MTOK * DMODEL];
__device__ __half g_ffh  [(size_t)MTOK * DFF];
// weights: Wt[N, K] fp16 K-major (single term)
__device__ __half g_wt_proj[640 * 256];    // rows: 0-255 value, 256-511 offs, 512-639 attn
__device__ __half g_wt_out [256 * 256];
__device__ __half g_wt_ff1 [1024 * 256];
__device__ __half g_wt_ff2 [256 * 1024];
__device__ float  g_bias_proj[640];

// ---------------- helpers ----------------
__device__ __forceinline__ uint32_t smem_u32(const void* p) {
    uint32_t a;
    asm("{ .reg .u64 t; cvta.to.shared.u64 t, %1; cvt.u32.u64 %0, t; }" : "=r"(a) : "l"(p));
    return a;
}
#define CP_ASYNC16(dst, src) \
    asm volatile("cp.async.cg.shared.global [%0], [%1], 16;\n" :: "r"(dst), "l"(src) : "memory")
#define CP_COMMIT() asm volatile("cp.async.commit_group;\n" ::: "memory")
#define CP_WAIT(n)  asm volatile("cp.async.wait_group %0;\n" :: "n"(n) : "memory")

__device__ __forceinline__ void ldmatrix_x4(uint32_t& r0, uint32_t& r1, uint32_t& r2, uint32_t& r3, uint32_t addr) {
    asm volatile("ldmatrix.sync.aligned.m8n8.x4.shared.b16 {%0,%1,%2,%3}, [%4];"
                 : "=r"(r0), "=r"(r1), "=r"(r2), "=r"(r3) : "r"(addr));
}
__device__ __forceinline__ void mma_f16(float* c, const uint32_t* a, const uint32_t* b) {
    asm volatile("mma.sync.aligned.m16n8k16.row.col.f32.f16.f16.f32 "
                 "{%0,%1,%2,%3}, {%4,%5,%6,%7}, {%8,%9}, {%0,%1,%2,%3};"
                 : "+f"(c[0]), "+f"(c[1]), "+f"(c[2]), "+f"(c[3])
                 : "r"(a[0]), "r"(a[1]), "r"(a[2]), "r"(a[3]), "r"(b[0]), "r"(b[1]));
}

// ---------------- fp16 warp-MMA GEMM, 4-stage cp.async pipeline ------------
// C = A[M,K] @ B[N,K]^T + bias. Tile 128x128, BK=32, 8 warps (4M x 2N).
// mode 0: Cf fp32 [M,N]. mode 1: Ch fp16 [M,N].
// mode 2: cols 0-255 -> Ch (value fp16, stride 256); 256-511 -> C2 (fp32, 256);
//         512-639 -> C3 (fp32, 128). bias indexed by global col.
#define PADS 40
#define STAGE_ELEMS (128 * PADS)
#define NSTAGE 4
#define GEMM_SMEM (2 * NSTAGE * STAGE_ELEMS * 2)   // 81920 bytes

__global__ __launch_bounds__(256, 2)
void gemm_mma(const __half* __restrict__ A, int lda,
              const __half* __restrict__ B, int ldb,
              const float* __restrict__ bias,
              float* __restrict__ Cf, __half* __restrict__ Ch,
              float* __restrict__ C2, float* __restrict__ C3,
              int M, int K, int N, int relu, int mode)
{
    extern __shared__ __align__(16) __half dynsmem[];

    const int tid  = threadIdx.x;
    const int wid  = tid >> 5;
    const int lane = tid & 31;
    const int wm   = wid & 3;
    const int wn   = wid >> 2;
    const int row0 = blockIdx.y * 128;
    const int col0 = blockIdx.x * 128;

    const uint32_t sbase = smem_u32(dynsmem);
    const int NC = K >> 5;   // BK = 32; requires NC >= 3

    float acc[2][8][4];
#pragma unroll
    for (int i = 0; i < 2; i++)
#pragma unroll
        for (int j = 0; j < 8; j++)
#pragma unroll
            for (int t = 0; t < 4; t++) acc[i][j][t] = 0.f;

#define LOAD_STAGE(buf, cc) do {                                              \
        int _kc = (cc) << 5;                                                  \
        uint32_t _dA = sbase + (buf) * (STAGE_ELEMS * 2);                     \
        uint32_t _dB = sbase + (NSTAGE + (buf)) * (STAGE_ELEMS * 2);          \
        _Pragma("unroll")                                                     \
        for (int _i = 0; _i < 2; ++_i) {                                      \
            int _c = tid + _i * 256;                                          \
            int _r = _c >> 2, _k8 = _c & 3;                                   \
            int _gr = row0 + _r; if (_gr >= M) _gr = M - 1;                   \
            CP_ASYNC16(_dA + (_r * PADS + _k8 * 8) * 2,                       \
                       A + (size_t)_gr * lda + _kc + _k8 * 8);                \
        }                                                                     \
        _Pragma("unroll")                                                     \
        for (int _i = 0; _i < 2; ++_i) {                                      \
            int _c = tid + _i * 256;                                          \
            int _r = _c >> 2, _k8 = _c & 3;                                   \
            CP_ASYNC16(_dB + (_r * PADS + _k8 * 8) * 2,                       \
                       B + (size_t)(col0 + _r) * ldb + _kc + _k8 * 8);        \
        }                                                                     \
    } while (0)

    LOAD_STAGE(0, 0); CP_COMMIT();
    LOAD_STAGE(1, 1); CP_COMMIT();
    LOAD_STAGE(2, 2); CP_COMMIT();

    for (int c = 0; c < NC; ++c) {
        const int buf = c & 3;
        CP_WAIT(2);
        __syncthreads();

        if (c + 3 < NC) LOAD_STAGE((c + 3) & 3, c + 3);
        CP_COMMIT();

        const uint32_t baseA = sbase + buf * (STAGE_ELEMS * 2);
        const uint32_t baseB = sbase + (NSTAGE + buf) * (STAGE_ELEMS * 2);

#pragma unroll
        for (int kk = 0; kk < 32; kk += 16) {
            uint32_t a[2][4];
#pragma unroll
            for (int mt = 0; mt < 2; mt++) {
                int r = wm * 32 + mt * 16 + (lane & 15);
                int kc = kk + ((lane & 16) ? 8 : 0);
                ldmatrix_x4(a[mt][0], a[mt][1], a[mt][2], a[mt][3],
                            baseA + (r * PADS + kc) * 2);
            }
            uint32_t b[8][2];
#pragma unroll
            for (int np = 0; np < 4; np++) {
                int n = wn * 64 + np * 16 + (lane & 7) + ((lane & 16) ? 8 : 0);
                int kc = kk + ((lane & 8) ? 8 : 0);
                ldmatrix_x4(b[2 * np][0], b[2 * np][1], b[2 * np + 1][0], b[2 * np + 1][1],
                            baseB + (n * PADS + kc) * 2);
            }
#pragma unroll
            for (int mt = 0; mt < 2; mt++)
#pragma unroll
                for (int nt = 0; nt < 8; nt++)
                    mma_f16(acc[mt][nt], a[mt], b[nt]);
        }
        __syncthreads();
    }

    // ---- epilogue ----
    float* outf = Cf;
    __half* outh = Ch;
    int ostride = N, coff = 0;
    int write_half = (mode == 1);
    if (mode == 2) {
        if (col0 < 256)      { outh = Ch; ostride = 256; coff = 0; write_half = 1; }
        else if (col0 < 512) { outf = C2; ostride = 256; coff = 256; }
        else                 { outf = C3; ostride = 128; coff = 512; }
    }

#pragma unroll
    for (int mt = 0; mt < 2; mt++) {
#pragma unroll
        for (int half_i = 0; half_i < 2; half_i++) {
            int r = row0 + wm * 32 + mt * 16 + (lane >> 2) + half_i * 8;
            if (r >= M) continue;
#pragma unroll
            for (int nt = 0; nt < 8; nt++) {
                int cidx = col0 + wn * 64 + nt * 8 + (lane & 3) * 2;
                float v0 = acc[mt][nt][half_i * 2 + 0] + bias[cidx];
                float v1 = acc[mt][nt][half_i * 2 + 1] + bias[cidx + 1];
                if (relu) { v0 = fmaxf(v0, 0.f); v1 = fmaxf(v1, 0.f); }
                if (write_half) {
                    __half2 hv;
                    hv.x = __float2half_rn(v0);
                    hv.y = __float2half_rn(v1);
                    *reinterpret_cast<__half2*>(outh + (size_t)r * ostride + (cidx - coff)) = hv;
                } else {
                    float2 o = make_float2(v0, v1);
                    *reinterpret_cast<float2*>(outf + (size_t)r * ostride + (cidx - coff)) = o;
                }
            }
        }
    }
#undef LOAD_STAGE
}

// ---------------- combined weight prep (single launch) ----------------
// W [K,N] fp32 -> Wt [N, K] fp16 transpose; plus bias concat.
__device__ __forceinline__ void wtr1(const float* __restrict__ W, __half* __restrict__ Wt,
                                     int K_, int N_, int i)
{
    int k = i / N_, n = i % N_;
    Wt[(size_t)n * K_ + k] = __float2half_rn(W[i]);
}

__global__ void prep_kernel(const float* __restrict__ vW, const float* __restrict__ oW,
                            const float* __restrict__ aW, const float* __restrict__ uW,
                            const float* __restrict__ f1W, const float* __restrict__ f2W,
                            const float* __restrict__ vb, const float* __restrict__ ob,
                            const float* __restrict__ ab,
                            __half* __restrict__ wtp, __half* __restrict__ wtu,
                            __half* __restrict__ wtf1, __half* __restrict__ wtf2,
                            float* __restrict__ biasp)
{
    int i = blockIdx.x * blockDim.x + threadIdx.x;
    if (i < 65536)       { wtr1(vW, wtp, 256, 256, i); return; }
    i -= 65536;
    if (i < 65536)       { wtr1(oW, wtp + 256 * 256, 256, 256, i); return; }
    i -= 65536;
    if (i < 32768)       { wtr1(aW, wtp + 512 * 256, 256, 128, i); return; }
    i -= 32768;
    if (i < 65536)       { wtr1(uW, wtu, 256, 256, i); return; }
    i -= 65536;
    if (i < 262144)      { wtr1(f1W, wtf1, 256, 1024, i); return; }
    i -= 262144;
    if (i < 262144)      { wtr1(f2W, wtf2, 1024, 256, i); return; }
    i -= 262144;
    if (i < 256)         { biasp[i] = vb[i]; return; }
    if (i < 512)         { biasp[i] = ob[i - 256]; return; }
    if (i < 640)         { biasp[i] = ab[i - 512]; return; }
}

// ---------------- q = src + pos (fp32 + fp16) ----------------
__global__ void add_split_kernel(const float* __restrict__ a, const float* __restrict__ b,
                                 float* __restrict__ q, __half* __restrict__ qh, int n)
{
    int i = blockIdx.x * blockDim.x + threadIdx.x;
    if (i >= n) return;
    float v = a[i] + b[i];
    q[i] = v;
    qh[i] = __float2half_rn(v);
}

// ---------------- MSDA bilinear sampling with fused softmax ----------------
// block = token, warp = head, lane = channel; softmax over the head's 16
// logits done in-register via shfl (lanes duplicate j = lane & 15).
__global__ __launch_bounds__(256)
void msda_kernel(const __half* __restrict__ value, const float* __restrict__ offs,
                 const float* __restrict__ aw, const float* __restrict__ ref,
                 const int* __restrict__ shapes, const int* __restrict__ starts,
                 __half* __restrict__ outh)
{
    const int tok = blockIdx.x;
    const int h = threadIdx.x >> 5;
    const int lane = threadIdx.x & 31;
    const int b = tok / LIN;

    // fused softmax over 16 logits of this (tok, head)
    float logit = aw[(size_t)tok * 128 + h * 16 + (lane & 15)];
    float m = logit;
#pragma unroll
    for (int o = 8; o; o >>= 1) m = fmaxf(m, __shfl_xor_sync(0xffffffffu, m, o, 16));
    float e = expf(logit - m);
    float s = e;
#pragma unroll
    for (int o = 8; o; o >>= 1) s += __shfl_xor_sync(0xffffffffu, s, o, 16);
    float wnorm = e / s;

    const float* refp = ref + (size_t)tok * (NLVL * 2);
    float acc = 0.f;

#pragma unroll
    for (int l = 0; l < NLVL; l++) {
        const int Hl = shapes[l * 2 + 0];
        const int Wl = shapes[l * 2 + 1];
        const int st = starts[l];
        const float fW = (float)Wl, fH = (float)Hl;
        const float rx = refp[l * 2 + 0];
        const float ry = refp[l * 2 + 1];

        const float* op = offs + (size_t)tok * 256 + (size_t)((h * NLVL + l) * NPTS) * 2;
        const size_t vbase = ((size_t)b * LIN + st) * DMODEL + h * DH + lane;

#pragma unroll
        for (int p = 0; p < NPTS; p++) {
            float ox = op[p * 2 + 0];
            float oy = op[p * 2 + 1];
            float a  = __shfl_sync(0xffffffffu, wnorm, l * NPTS + p, 16);
            float x = (rx + ox / fW) * fW - 0.5f;
            float y = (ry + oy / fH) * fH - 0.5f;
            float x0f = floorf(x), y0f = floorf(y);
            float dx = x - x0f, dy = y - y0f;
            int x0 = (int)x0f, y0 = (int)y0f;

            float w00 = (1.f - dx) * (1.f - dy);
            float w10 = dx * (1.f - dy);
            float w01 = (1.f - dx) * dy;
            float w11 = dx * dy;

            bool xv0 = (x0 >= 0) && (x0 < Wl);
            bool xv1 = (x0 + 1 >= 0) && (x0 + 1 < Wl);
            bool yv0 = (y0 >= 0) && (y0 < Hl);
            bool yv1 = (y0 + 1 >= 0) && (y0 + 1 < Hl);

            float v00 = 0.f, v10 = 0.f, v01 = 0.f, v11 = 0.f;
            if (yv0 && xv0) v00 = __half2float(value[vbase + (size_t)(y0 * Wl + x0) * DMODEL]);
            if (yv0 && xv1) v10 = __half2float(value[vbase + (size_t)(y0 * Wl + x0 + 1) * DMODEL]);
            if (yv1 && xv0) v01 = __half2float(value[vbase + (size_t)((y0 + 1) * Wl + x0) * DMODEL]);
            if (yv1 && xv1) v11 = __half2float(value[vbase + (size_t)((y0 + 1) * Wl + x0 + 1) * DMODEL]);

            acc = fmaf(a, w00 * v00 + w10 * v10 + w01 * v01 + w11 * v11, acc);
        }
    }
    outh[(size_t)tok * DMODEL + h * DH + lane] = __float2half_rn(acc);
}

// ---------------- fused residual add + LayerNorm (+ optional fp16 copy) ----
__global__ __launch_bounds__(256)
void add_ln_kernel(const float* __restrict__ a, const float* __restrict__ r,
                   const float* __restrict__ g, const float* __restrict__ bb,
                   float* __restrict__ out, __half* __restrict__ outh)
{
    const int tok = blockIdx.x;
    const int i = threadIdx.x;
    float v = a[(size_t)tok * DMODEL + i] + r[(size_t)tok * DMODEL + i];

    __shared__ float sh[8];
    float s = v;
#pragma unroll
    for (int o = 16; o; o >>= 1) s += __shfl_xor_sync(0xffffffffu, s, o);
    if ((i & 31) == 0) sh[i >> 5] = s;
    __syncthreads();
    float tot = 0.f;
#pragma unroll
    for (int w = 0; w < 8; w++) tot += sh[w];
    float mean = tot * (1.f / 256.f);
    __syncthreads();

    float d = v - mean;
    float s2 = d * d;
#pragma unroll
    for (int o = 16; o; o >>= 1) s2 += __shfl_xor_sync(0xffffffffu, s2, o);
    if ((i & 31) == 0) sh[i >> 5] = s2;
    __syncthreads();
    float tot2 = 0.f;
#pragma unroll
    for (int w = 0; w < 8; w++) tot2 += sh[w];
    float var = tot2 * (1.f / 256.f);

    float o = d * rsqrtf(var + 1e-5f) * g[i] + bb[i];
    out[(size_t)tok * DMODEL + i] = o;
    if (outh) outh[(size_t)tok * DMODEL + i] = __float2half_rn(o);
}

// ---------------- launch ----------------
extern "C" void kernel_launch(void* const* d_in, const int* in_sizes, int n_in,
                              void* d_out, int out_size)
{
    const float* src    = (const float*)d_in[0];
    const float* pos    = (const float*)d_in[1];
    const float* refpts = (const float*)d_in[2];
    const int*   shapes = (const int*)  d_in[3];
    const int*   starts = (const int*)  d_in[4];
    const float* value_w = (const float*)d_in[5];
    const float* value_b = (const float*)d_in[6];
    const float* offs_w  = (const float*)d_in[7];
    const float* offs_b  = (const float*)d_in[8];
    const float* attn_w  = (const float*)d_in[9];
    const float* attn_b  = (const float*)d_in[10];
    const float* out_w   = (const float*)d_in[11];
    const float* out_b   = (const float*)d_in[12];
    const float* ln1_g   = (const float*)d_in[13];
    const float* ln1_b   = (const float*)d_in[14];
    const float* ff1_w   = (const float*)d_in[15];
    const float* ff1_b   = (const float*)d_in[16];
    const float* ff2_w   = (const float*)d_in[17];
    const float* ff2_b   = (const float*)d_in[18];
    const float* ln2_g   = (const float*)d_in[19];
    const float* ln2_b   = (const float*)d_in[20];
    float* outp = (float*)d_out;

    float *q, *offs, *aw, *src2, *x, *biasp;
    __half *qh, *value, *msdah, *xh, *ffh;
    __half *wtp, *wtu, *wtf1, *wtf2;
    cudaGetSymbolAddress((void**)&q,     g_q);
    cudaGetSymbolAddress((void**)&qh,    g_qh);
    cudaGetSymbolAddress((void**)&value, g_value);
    cudaGetSymbolAddress((void**)&offs,  g_offs);
    cudaGetSymbolAddress((void**)&aw,    g_aw);
    cudaGetSymbolAddress((void**)&msdah, g_msdah);
    cudaGetSymbolAddress((void**)&src2,  g_src2);
    cudaGetSymbolAddress((void**)&x,     g_x);
    cudaGetSymbolAddress((void**)&xh,    g_xh);
    cudaGetSymbolAddress((void**)&ffh,   g_ffh);
    cudaGetSymbolAddress((void**)&wtp,   g_wt_proj);
    cudaGetSymbolAddress((void**)&wtu,   g_wt_out);
    cudaGetSymbolAddress((void**)&wtf1,  g_wt_ff1);
    cudaGetSymbolAddress((void**)&wtf2,  g_wt_ff2);
    cudaGetSymbolAddress((void**)&biasp, g_bias_proj);

    cudaFuncSetAttribute(gemm_mma, cudaFuncAttributeMaxDynamicSharedMemorySize, GEMM_SMEM);

    const int M = MTOK;
    const int gy = (M + 127) / 128;

    // 0. all weight prep in one launch (754304 work items)
    prep_kernel<<<(754304 + 255) / 256, 256>>>(value_w, offs_w, attn_w, out_w, ff1_w, ff2_w,
                                               value_b, offs_b, attn_b,
                                               wtp, wtu, wtf1, wtf2, biasp);

    // 1. q = src + pos
    add_split_kernel<<<(M * DMODEL + 255) / 256, 256>>>(src, pos, q, qh, M * DMODEL);

    // 2. fused projections: [value(fp16) | offs | aw] = q @ Wp^T
    gemm_mma<<<dim3(5, gy), 256, GEMM_SMEM>>>(qh, 256, wtp, 256, biasp,
                                              nullptr, value, offs, aw, M, 256, 640, 0, 2);

    // 3. deformable sampling with fused softmax
    msda_kernel<<<M, 256>>>(value, offs, aw, refpts, shapes, starts, msdah);

    // 4. output projection: src2 = msda @ out_w + out_b
    gemm_mma<<<dim3(2, gy), 256, GEMM_SMEM>>>(msdah, 256, wtu, 256, out_b,
                                              src2, nullptr, nullptr, nullptr, M, 256, 256, 0, 0);

    // 5. x = LN(q + src2)  (+ fp16 copy)
    add_ln_kernel<<<M, 256>>>(q, src2, ln1_g, ln1_b, x, xh);

    // 6. ffh = relu(x @ ff1_w + ff1_b) -> fp16
    gemm_mma<<<dim3(8, gy), 256, GEMM_SMEM>>>(xh, 256, wtf1, 256, ff1_b,
                                              nullptr, ffh, nullptr, nullptr, M, 256, 1024, 1, 1);

    // 7. f = ffh @ ff2_w + ff2_b  (into 'offs' buffer)
    gemm_mma<<<dim3(2, gy), 256, GEMM_SMEM>>>(ffh, 1024, wtf2, 1024, ff2_b,
                                              offs, nullptr, nullptr, nullptr, M, 1024, 256, 0, 0);

    // 8. out = LN(x + f)
    add_ln_kernel<<<M, 256>>>(x, offs, ln2_g, ln2_b, outp, nullptr);
}

// round 7
// speedup vs baseline: 4.3394x; 1.7329x over previous
#include <cuda_runtime.h>
#include <cuda_fp16.h>
#include <cstdint>
#include <math.h>

// ---------------- problem constants ----------------
#define Bq    4
#define LIN   13294
#define MTOK  (Bq * LIN)      // 53176
#define DMODEL 256
#define NHEAD 8
#define NLVL  4
#define NPTS  4
#define DH    32
#define DFF   1024

// ---------------- scratch (device globals) ----------------
__device__ float  g_q    [(size_t)MTOK * DMODEL];
__device__ __half g_qh   [(size_t)MTOK * DMODEL];
__device__ __half g_value[(size_t)MTOK * DMODEL];
__device__ float  g_offs [(size_t)MTOK * DMODEL];   // reused for ff2 out
__device__ float  g_aw   [(size_t)MTOK * 128];      // raw logits
__device__ __half g_msdah[(size_t)MTOK * DMODEL];
__device__ float  g_src2 [(size_t)MTOK * DMODEL];
__device__ float  g_x    [(size_t)MTOK * DMODEL];
__device__ __half g_xh   [(size_t)MTOK * DMODEL];
__device__ __half g_ffh  [(size_t)MTOK * DFF];
// weights: Wt[N, K] fp16 K-major
__device__ __half g_wt_proj[640 * 256];    // rows: 0-255 value, 256-511 offs, 512-639 attn
__device__ __half g_wt_out [256 * 256];
__device__ __half g_wt_ff1 [1024 * 256];
__device__ __half g_wt_ff2 [256 * 1024];
__device__ float  g_bias_proj[640];

// ---------------- helpers ----------------
__device__ __forceinline__ uint32_t smem_u32(const void* p) {
    uint32_t a;
    asm("{ .reg .u64 t; cvta.to.shared.u64 t, %1; cvt.u32.u64 %0, t; }" : "=r"(a) : "l"(p));
    return a;
}
#define CP_ASYNC16(dst, src) \
    asm volatile("cp.async.cg.shared.global [%0], [%1], 16;\n" :: "r"(dst), "l"(src) : "memory")
#define CP_COMMIT() asm volatile("cp.async.commit_group;\n" ::: "memory")
#define CP_WAIT(n)  asm volatile("cp.async.wait_group %0;\n" :: "n"(n) : "memory")

__device__ __forceinline__ void ldmatrix_x4(uint32_t& r0, uint32_t& r1, uint32_t& r2, uint32_t& r3, uint32_t addr) {
    asm volatile("ldmatrix.sync.aligned.m8n8.x4.shared.b16 {%0,%1,%2,%3}, [%4];"
                 : "=r"(r0), "=r"(r1), "=r"(r2), "=r"(r3) : "r"(addr));
}
__device__ __forceinline__ void mma_f16(float* c, const uint32_t* a, const uint32_t* b) {
    asm volatile("mma.sync.aligned.m16n8k16.row.col.f32.f16.f16.f32 "
                 "{%0,%1,%2,%3}, {%4,%5,%6,%7}, {%8,%9}, {%0,%1,%2,%3};"
                 : "+f"(c[0]), "+f"(c[1]), "+f"(c[2]), "+f"(c[3])
                 : "r"(a[0]), "r"(a[1]), "r"(a[2]), "r"(a[3]), "r"(b[0]), "r"(b[1]));
}

// ---------------- fp16 warp-MMA GEMM, 4-stage cp.async pipeline ------------
#define PADS 40
#define STAGE_ELEMS (128 * PADS)
#define NSTAGE 4
#define GEMM_SMEM (2 * NSTAGE * STAGE_ELEMS * 2)   // 81920 bytes

__global__ __launch_bounds__(256, 2)
void gemm_mma(const __half* __restrict__ A, int lda,
              const __half* __restrict__ B, int ldb,
              const float* __restrict__ bias,
              float* __restrict__ Cf, __half* __restrict__ Ch,
              float* __restrict__ C2, float* __restrict__ C3,
              int M, int K, int N, int relu, int mode)
{
    extern __shared__ __align__(16) __half dynsmem[];

    const int tid  = threadIdx.x;
    const int wid  = tid >> 5;
    const int lane = tid & 31;
    const int wm   = wid & 3;
    const int wn   = wid >> 2;
    const int row0 = blockIdx.y * 128;
    const int col0 = blockIdx.x * 128;

    const uint32_t sbase = smem_u32(dynsmem);
    const int NC = K >> 5;

    float acc[2][8][4];
#pragma unroll
    for (int i = 0; i < 2; i++)
#pragma unroll
        for (int j = 0; j < 8; j++)
#pragma unroll
            for (int t = 0; t < 4; t++) acc[i][j][t] = 0.f;

#define LOAD_STAGE(buf, cc) do {                                              \
        int _kc = (cc) << 5;                                                  \
        uint32_t _dA = sbase + (buf) * (STAGE_ELEMS * 2);                     \
        uint32_t _dB = sbase + (NSTAGE + (buf)) * (STAGE_ELEMS * 2);          \
        _Pragma("unroll")                                                     \
        for (int _i = 0; _i < 2; ++_i) {                                      \
            int _c = tid + _i * 256;                                          \
            int _r = _c >> 2, _k8 = _c & 3;                                   \
            int _gr = row0 + _r; if (_gr >= M) _gr = M - 1;                   \
            CP_ASYNC16(_dA + (_r * PADS + _k8 * 8) * 2,                       \
                       A + (size_t)_gr * lda + _kc + _k8 * 8);                \
        }                                                                     \
        _Pragma("unroll")                                                     \
        for (int _i = 0; _i < 2; ++_i) {                                      \
            int _c = tid + _i * 256;                                          \
            int _r = _c >> 2, _k8 = _c & 3;                                   \
            CP_ASYNC16(_dB + (_r * PADS + _k8 * 8) * 2,                       \
                       B + (size_t)(col0 + _r) * ldb + _kc + _k8 * 8);        \
        }                                                                     \
    } while (0)

    LOAD_STAGE(0, 0); CP_COMMIT();
    LOAD_STAGE(1, 1); CP_COMMIT();
    LOAD_STAGE(2, 2); CP_COMMIT();

    for (int c = 0; c < NC; ++c) {
        const int buf = c & 3;
        CP_WAIT(2);
        __syncthreads();

        if (c + 3 < NC) LOAD_STAGE((c + 3) & 3, c + 3);
        CP_COMMIT();

        const uint32_t baseA = sbase + buf * (STAGE_ELEMS * 2);
        const uint32_t baseB = sbase + (NSTAGE + buf) * (STAGE_ELEMS * 2);

#pragma unroll
        for (int kk = 0; kk < 32; kk += 16) {
            uint32_t a[2][4];
#pragma unroll
            for (int mt = 0; mt < 2; mt++) {
                int r = wm * 32 + mt * 16 + (lane & 15);
                int kc = kk + ((lane & 16) ? 8 : 0);
                ldmatrix_x4(a[mt][0], a[mt][1], a[mt][2], a[mt][3],
                            baseA + (r * PADS + kc) * 2);
            }
            uint32_t b[8][2];
#pragma unroll
            for (int np = 0; np < 4; np++) {
                int n = wn * 64 + np * 16 + (lane & 7) + ((lane & 16) ? 8 : 0);
                int kc = kk + ((lane & 8) ? 8 : 0);
                ldmatrix_x4(b[2 * np][0], b[2 * np][1], b[2 * np + 1][0], b[2 * np + 1][1],
                            baseB + (n * PADS + kc) * 2);
            }
#pragma unroll
            for (int mt = 0; mt < 2; mt++)
#pragma unroll
                for (int nt = 0; nt < 8; nt++)
                    mma_f16(acc[mt][nt], a[mt], b[nt]);
        }
        __syncthreads();
    }

    // ---- epilogue ----
    float* outf = Cf;
    __half* outh = Ch;
    int ostride = N, coff = 0;
    int write_half = (mode == 1);
    if (mode == 2) {
        if (col0 < 256)      { outh = Ch; ostride = 256; coff = 0; write_half = 1; }
        else if (col0 < 512) { outf = C2; ostride = 256; coff = 256; }
        else                 { outf = C3; ostride = 128; coff = 512; }
    }

#pragma unroll
    for (int mt = 0; mt < 2; mt++) {
#pragma unroll
        for (int half_i = 0; half_i < 2; half_i++) {
            int r = row0 + wm * 32 + mt * 16 + (lane >> 2) + half_i * 8;
            if (r >= M) continue;
#pragma unroll
            for (int nt = 0; nt < 8; nt++) {
                int cidx = col0 + wn * 64 + nt * 8 + (lane & 3) * 2;
                float v0 = acc[mt][nt][half_i * 2 + 0] + bias[cidx];
                float v1 = acc[mt][nt][half_i * 2 + 1] + bias[cidx + 1];
                if (relu) { v0 = fmaxf(v0, 0.f); v1 = fmaxf(v1, 0.f); }
                if (write_half) {
                    __half2 hv;
                    hv.x = __float2half_rn(v0);
                    hv.y = __float2half_rn(v1);
                    *reinterpret_cast<__half2*>(outh + (size_t)r * ostride + (cidx - coff)) = hv;
                } else {
                    float2 o = make_float2(v0, v1);
                    *reinterpret_cast<float2*>(outf + (size_t)r * ostride + (cidx - coff)) = o;
                }
            }
        }
    }
#undef LOAD_STAGE
}

// ---------------- combined weight prep (single launch) ----------------
__device__ __forceinline__ void wtr1(const float* __restrict__ W, __half* __restrict__ Wt,
                                     int K_, int N_, int i)
{
    int k = i / N_, n = i % N_;
    Wt[(size_t)n * K_ + k] = __float2half_rn(W[i]);
}

__global__ void prep_kernel(const float* __restrict__ vW, const float* __restrict__ oW,
                            const float* __restrict__ aW, const float* __restrict__ uW,
                            const float* __restrict__ f1W, const float* __restrict__ f2W,
                            const float* __restrict__ vb, const float* __restrict__ ob,
                            const float* __restrict__ ab,
                            __half* __restrict__ wtp, __half* __restrict__ wtu,
                            __half* __restrict__ wtf1, __half* __restrict__ wtf2,
                            float* __restrict__ biasp)
{
    int i = blockIdx.x * blockDim.x + threadIdx.x;
    if (i < 65536)       { wtr1(vW, wtp, 256, 256, i); return; }
    i -= 65536;
    if (i < 65536)       { wtr1(oW, wtp + 256 * 256, 256, 256, i); return; }
    i -= 65536;
    if (i < 32768)       { wtr1(aW, wtp + 512 * 256, 256, 128, i); return; }
    i -= 32768;
    if (i < 65536)       { wtr1(uW, wtu, 256, 256, i); return; }
    i -= 65536;
    if (i < 262144)      { wtr1(f1W, wtf1, 256, 1024, i); return; }
    i -= 262144;
    if (i < 262144)      { wtr1(f2W, wtf2, 1024, 256, i); return; }
    i -= 262144;
    if (i < 256)         { biasp[i] = vb[i]; return; }
    if (i < 512)         { biasp[i] = ob[i - 256]; return; }
    if (i < 640)         { biasp[i] = ab[i - 512]; return; }
}

// ---------------- q = src + pos (fp32 + fp16) ----------------
__global__ void add_split_kernel(const float* __restrict__ a, const float* __restrict__ b,
                                 float* __restrict__ q, __half* __restrict__ qh, int n)
{
    int i = blockIdx.x * blockDim.x + threadIdx.x;
    if (i >= n) return;
    float v = a[i] + b[i];
    q[i] = v;
    qh[i] = __float2half_rn(v);
}

// ---------------- MSDA: fused softmax + deduplicated sampling --------------
// block = token, warp = head. Lane j (=lane&15) precomputes point j's corner
// indices + softmax-scaled bilinear weights. Inner loop: 8 point-pairs; the
// point state is shuffled from lane pt; each lane gathers a __half2 (2
// channels) per corner. Cross-half reduce at the end.
__global__ __launch_bounds__(256)
void msda_kernel(const __half* __restrict__ value, const float* __restrict__ offs,
                 const float* __restrict__ aw, const float* __restrict__ ref,
                 const int* __restrict__ shapes, const int* __restrict__ starts,
                 __half* __restrict__ outh)
{
    const int tok = blockIdx.x;
    const int h = threadIdx.x >> 5;
    const int lane = threadIdx.x & 31;
    const int j = lane & 15;          // point this lane precomputes
    const int b = tok / LIN;
    const int l = j >> 2;             // level of point j

    // ---- per-point precompute (duplicated in both 16-lane halves) ----
    const int Hl = shapes[l * 2 + 0];
    const int Wl = shapes[l * 2 + 1];
    const int st = starts[l];
    const float fW = (float)Wl, fH = (float)Hl;
    const float rx = ref[(size_t)tok * 8 + l * 2 + 0];
    const float ry = ref[(size_t)tok * 8 + l * 2 + 1];
    const float2 off = *reinterpret_cast<const float2*>(offs + (size_t)tok * 256 + h * 32 + 2 * j);

    // softmax over the head's 16 logits
    float logit = aw[(size_t)tok * 128 + h * 16 + j];
    float m = logit;
#pragma unroll
    for (int o = 8; o; o >>= 1) m = fmaxf(m, __shfl_xor_sync(0xffffffffu, m, o, 16));
    float e = expf(logit - m);
    float s = e;
#pragma unroll
    for (int o = 8; o; o >>= 1) s += __shfl_xor_sync(0xffffffffu, s, o, 16);
    float a = e / s;

    float x = (rx + off.x / fW) * fW - 0.5f;
    float y = (ry + off.y / fH) * fH - 0.5f;
    float x0f = floorf(x), y0f = floorf(y);
    float dx = x - x0f, dy = y - y0f;
    int x0 = (int)x0f, y0 = (int)y0f;
    int x1 = x0 + 1, y1 = y0 + 1;

    bool xv0 = (x0 >= 0) & (x0 < Wl);
    bool xv1 = (x1 >= 0) & (x1 < Wl);
    bool yv0 = (y0 >= 0) & (y0 < Hl);
    bool yv1 = (y1 >= 0) & (y1 < Hl);

    float w00 = (xv0 && yv0) ? a * (1.f - dx) * (1.f - dy) : 0.f;
    float w10 = (xv1 && yv0) ? a * dx * (1.f - dy) : 0.f;
    float w01 = (xv0 && yv1) ? a * (1.f - dx) * dy : 0.f;
    float w11 = (xv1 && yv1) ? a * dx * dy : 0.f;

    int cx0 = min(max(x0, 0), Wl - 1), cx1 = min(max(x1, 0), Wl - 1);
    int cy0 = min(max(y0, 0), Hl - 1), cy1 = min(max(y1, 0), Hl - 1);
    const int base = b * LIN + st;
    int i00 = base + cy0 * Wl + cx0;
    int i10 = base + cy0 * Wl + cx1;
    int i01 = base + cy1 * Wl + cx0;
    int i11 = base + cy1 * Wl + cx1;

    // ---- gather loop: 8 point-pairs, half2 channels ----
    const __half* vch = value + h * DH + (lane & 15) * 2;   // this lane's channel pair
    float accx = 0.f, accy = 0.f;

#pragma unroll
    for (int pg = 0; pg < 8; pg++) {
        int pt = pg * 2 + (lane >> 4);
        int a00 = __shfl_sync(0xffffffffu, i00, pt);
        int a10 = __shfl_sync(0xffffffffu, i10, pt);
        int a01 = __shfl_sync(0xffffffffu, i01, pt);
        int a11 = __shfl_sync(0xffffffffu, i11, pt);
        float u00 = __shfl_sync(0xffffffffu, w00, pt);
        float u10 = __shfl_sync(0xffffffffu, w10, pt);
        float u01 = __shfl_sync(0xffffffffu, w01, pt);
        float u11 = __shfl_sync(0xffffffffu, w11, pt);

        float2 f00 = __half22float2(*reinterpret_cast<const __half2*>(vch + (size_t)a00 * DMODEL));
        float2 f10 = __half22float2(*reinterpret_cast<const __half2*>(vch + (size_t)a10 * DMODEL));
        float2 f01 = __half22float2(*reinterpret_cast<const __half2*>(vch + (size_t)a01 * DMODEL));
        float2 f11 = __half22float2(*reinterpret_cast<const __half2*>(vch + (size_t)a11 * DMODEL));

        accx = fmaf(u00, f00.x, fmaf(u10, f10.x, fmaf(u01, f01.x, fmaf(u11, f11.x, accx))));
        accy = fmaf(u00, f00.y, fmaf(u10, f10.y, fmaf(u01, f01.y, fmaf(u11, f11.y, accy))));
    }

    accx += __shfl_xor_sync(0xffffffffu, accx, 16);
    accy += __shfl_xor_sync(0xffffffffu, accy, 16);

    if (lane < 16) {
        __half2 o = __floats2half2_rn(accx, accy);
        *reinterpret_cast<__half2*>(outh + (size_t)tok * DMODEL + h * DH + lane * 2) = o;
    }
}

// ---------------- fused residual add + LayerNorm (+ optional fp16 copy) ----
__global__ __launch_bounds__(256)
void add_ln_kernel(const float* __restrict__ a, const float* __restrict__ r,
                   const float* __restrict__ g, const float* __restrict__ bb,
                   float* __restrict__ out, __half* __restrict__ outh)
{
    const int tok = blockIdx.x;
    const int i = threadIdx.x;
    float v = a[(size_t)tok * DMODEL + i] + r[(size_t)tok * DMODEL + i];

    __shared__ float sh[8];
    float s = v;
#pragma unroll
    for (int o = 16; o; o >>= 1) s += __shfl_xor_sync(0xffffffffu, s, o);
    if ((i & 31) == 0) sh[i >> 5] = s;
    __syncthreads();
    float tot = 0.f;
#pragma unroll
    for (int w = 0; w < 8; w++) tot += sh[w];
    float mean = tot * (1.f / 256.f);
    __syncthreads();

    float d = v - mean;
    float s2 = d * d;
#pragma unroll
    for (int o = 16; o; o >>= 1) s2 += __shfl_xor_sync(0xffffffffu, s2, o);
    if ((i & 31) == 0) sh[i >> 5] = s2;
    __syncthreads();
    float tot2 = 0.f;
#pragma unroll
    for (int w = 0; w < 8; w++) tot2 += sh[w];
    float var = tot2 * (1.f / 256.f);

    float o = d * rsqrtf(var + 1e-5f) * g[i] + bb[i];
    out[(size_t)tok * DMODEL + i] = o;
    if (outh) outh[(size_t)tok * DMODEL + i] = __float2half_rn(o);
}

// ---------------- launch ----------------
extern "C" void kernel_launch(void* const* d_in, const int* in_sizes, int n_in,
                              void* d_out, int out_size)
{
    const float* src    = (const float*)d_in[0];
    const float* pos    = (const float*)d_in[1];
    const float* refpts = (const float*)d_in[2];
    const int*   shapes = (const int*)  d_in[3];
    const int*   starts = (const int*)  d_in[4];
    const float* value_w = (const float*)d_in[5];
    const float* value_b = (const float*)d_in[6];
    const float* offs_w  = (const float*)d_in[7];
    const float* offs_b  = (const float*)d_in[8];
    const float* attn_w  = (const float*)d_in[9];
    const float* attn_b  = (const float*)d_in[10];
    const float* out_w   = (const float*)d_in[11];
    const float* out_b   = (const float*)d_in[12];
    const float* ln1_g   = (const float*)d_in[13];
    const float* ln1_b   = (const float*)d_in[14];
    const float* ff1_w   = (const float*)d_in[15];
    const float* ff1_b   = (const float*)d_in[16];
    const float* ff2_w   = (const float*)d_in[17];
    const float* ff2_b   = (const float*)d_in[18];
    const float* ln2_g   = (const float*)d_in[19];
    const float* ln2_b   = (const float*)d_in[20];
    float* outp = (float*)d_out;

    float *q, *offs, *aw, *src2, *x, *biasp;
    __half *qh, *value, *msdah, *xh, *ffh;
    __half *wtp, *wtu, *wtf1, *wtf2;
    cudaGetSymbolAddress((void**)&q,     g_q);
    cudaGetSymbolAddress((void**)&qh,    g_qh);
    cudaGetSymbolAddress((void**)&value, g_value);
    cudaGetSymbolAddress((void**)&offs,  g_offs);
    cudaGetSymbolAddress((void**)&aw,    g_aw);
    cudaGetSymbolAddress((void**)&msdah, g_msdah);
    cudaGetSymbolAddress((void**)&src2,  g_src2);
    cudaGetSymbolAddress((void**)&x,     g_x);
    cudaGetSymbolAddress((void**)&xh,    g_xh);
    cudaGetSymbolAddress((void**)&ffh,   g_ffh);
    cudaGetSymbolAddress((void**)&wtp,   g_wt_proj);
    cudaGetSymbolAddress((void**)&wtu,   g_wt_out);
    cudaGetSymbolAddress((void**)&wtf1,  g_wt_ff1);
    cudaGetSymbolAddress((void**)&wtf2,  g_wt_ff2);
    cudaGetSymbolAddress((void**)&biasp, g_bias_proj);

    cudaFuncSetAttribute(gemm_mma, cudaFuncAttributeMaxDynamicSharedMemorySize, GEMM_SMEM);

    const int M = MTOK;
    const int gy = (M + 127) / 128;

    // 0. all weight prep in one launch
    prep_kernel<<<(754304 + 255) / 256, 256>>>(value_w, offs_w, attn_w, out_w, ff1_w, ff2_w,
                                               value_b, offs_b, attn_b,
                                               wtp, wtu, wtf1, wtf2, biasp);

    // 1. q = src + pos
    add_split_kernel<<<(M * DMODEL + 255) / 256, 256>>>(src, pos, q, qh, M * DMODEL);

    // 2. fused projections: [value(fp16) | offs | aw] = q @ Wp^T
    gemm_mma<<<dim3(5, gy), 256, GEMM_SMEM>>>(qh, 256, wtp, 256, biasp,
                                              nullptr, value, offs, aw, M, 256, 640, 0, 2);

    // 3. deformable sampling with fused softmax
    msda_kernel<<<M, 256>>>(value, offs, aw, refpts, shapes, starts, msdah);

    // 4. output projection: src2 = msda @ out_w + out_b
    gemm_mma<<<dim3(2, gy), 256, GEMM_SMEM>>>(msdah, 256, wtu, 256, out_b,
                                              src2, nullptr, nullptr, nullptr, M, 256, 256, 0, 0);

    // 5. x = LN(q + src2)  (+ fp16 copy)
    add_ln_kernel<<<M, 256>>>(q, src2, ln1_g, ln1_b, x, xh);

    // 6. ffh = relu(x @ ff1_w + ff1_b) -> fp16
    gemm_mma<<<dim3(8, gy), 256, GEMM_SMEM>>>(xh, 256, wtf1, 256, ff1_b,
                                              nullptr, ffh, nullptr, nullptr, M, 256, 1024, 1, 1);

    // 7. f = ffh @ ff2_w + ff2_b  (into 'offs' buffer)
    gemm_mma<<<dim3(2, gy), 256, GEMM_SMEM>>>(ffh, 1024, wtf2, 1024, ff2_b,
                                              offs, nullptr, nullptr, nullptr, M, 1024, 256, 0, 0);

    // 8. out = LN(x + f)
    add_ln_kernel<<<M, 256>>>(x, offs, ln2_g, ln2_b, outp, nullptr);
}

// round 8
// speedup vs baseline: 5.1708x; 1.1916x over previous
#include <cuda_runtime.h>
#include <cuda_fp16.h>
#include <cstdint>
#include <math.h>

// ---------------- problem constants ----------------
#define Bq    4
#define LIN   13294
#define MTOK  (Bq * LIN)      // 53176
#define DMODEL 256
#define NHEAD 8
#define NLVL  4
#define NPTS  4
#define DH    32
#define DFF   1024

// ---------------- scratch (device globals) ----------------
__device__ float  g_q    [(size_t)MTOK * DMODEL];
__device__ __half g_qh   [(size_t)MTOK * DMODEL];
__device__ __half g_value[(size_t)MTOK * DMODEL];
__device__ float  g_offs [(size_t)MTOK * DMODEL];   // reused for ff2 out
__device__ float  g_aw   [(size_t)MTOK * 128];      // raw logits
__device__ __half g_msdah[(size_t)MTOK * DMODEL];
__device__ float  g_src2 [(size_t)MTOK * DMODEL];
__device__ float  g_x    [(size_t)MTOK * DMODEL];
__device__ __half g_xh   [(size_t)MTOK * DMODEL];
__device__ __half g_ffh  [(size_t)MTOK * DFF];
// weights: Wt[N, K] fp16 K-major
__device__ __half g_wt_proj[640 * 256];
__device__ __half g_wt_out [256 * 256];
__device__ __half g_wt_ff1 [1024 * 256];
__device__ __half g_wt_ff2 [256 * 1024];
__device__ float  g_bias_proj[640];

// ---------------- helpers ----------------
__device__ __forceinline__ uint32_t smem_u32(const void* p) {
    uint32_t a;
    asm("{ .reg .u64 t; cvta.to.shared.u64 t, %1; cvt.u32.u64 %0, t; }" : "=r"(a) : "l"(p));
    return a;
}
#define CP_ASYNC16(dst, src) \
    asm volatile("cp.async.cg.shared.global [%0], [%1], 16;\n" :: "r"(dst), "l"(src) : "memory")
#define CP_COMMIT() asm volatile("cp.async.commit_group;\n" ::: "memory")
#define CP_WAIT(n)  asm volatile("cp.async.wait_group %0;\n" :: "n"(n) : "memory")

__device__ __forceinline__ void ldmatrix_x4(uint32_t& r0, uint32_t& r1, uint32_t& r2, uint32_t& r3, uint32_t addr) {
    asm volatile("ldmatrix.sync.aligned.m8n8.x4.shared.b16 {%0,%1,%2,%3}, [%4];"
                 : "=r"(r0), "=r"(r1), "=r"(r2), "=r"(r3) : "r"(addr));
}
__device__ __forceinline__ void mma_f16(float* c, const uint32_t* a, const uint32_t* b) {
    asm volatile("mma.sync.aligned.m16n8k16.row.col.f32.f16.f16.f32 "
                 "{%0,%1,%2,%3}, {%4,%5,%6,%7}, {%8,%9}, {%0,%1,%2,%3};"
                 : "+f"(c[0]), "+f"(c[1]), "+f"(c[2]), "+f"(c[3])
                 : "r"(a[0]), "r"(a[1]), "r"(a[2]), "r"(a[3]), "r"(b[0]), "r"(b[1]));
}

// ---------------- fp16 warp-MMA GEMM, 4-stage cp.async pipeline ------------
#define PADS 40
#define STAGE_ELEMS (128 * PADS)
#define NSTAGE 4
#define GEMM_SMEM (2 * NSTAGE * STAGE_ELEMS * 2)   // 81920 bytes

__global__ __launch_bounds__(256, 2)
void gemm_mma(const __half* __restrict__ A, int lda,
              const __half* __restrict__ B, int ldb,
              const float* __restrict__ bias,
              float* __restrict__ Cf, __half* __restrict__ Ch,
              float* __restrict__ C2, float* __restrict__ C3,
              int M, int K, int N, int relu, int mode)
{
    extern __shared__ __align__(16) __half dynsmem[];

    const int tid  = threadIdx.x;
    const int wid  = tid >> 5;
    const int lane = tid & 31;
    const int wm   = wid & 3;
    const int wn   = wid >> 2;
    const int row0 = blockIdx.y * 128;
    const int col0 = blockIdx.x * 128;

    const uint32_t sbase = smem_u32(dynsmem);
    const int NC = K >> 5;

    float acc[2][8][4];
#pragma unroll
    for (int i = 0; i < 2; i++)
#pragma unroll
        for (int j = 0; j < 8; j++)
#pragma unroll
            for (int t = 0; t < 4; t++) acc[i][j][t] = 0.f;

#define LOAD_STAGE(buf, cc) do {                                              \
        int _kc = (cc) << 5;                                                  \
        uint32_t _dA = sbase + (buf) * (STAGE_ELEMS * 2);                     \
        uint32_t _dB = sbase + (NSTAGE + (buf)) * (STAGE_ELEMS * 2);          \
        _Pragma("unroll")                                                     \
        for (int _i = 0; _i < 2; ++_i) {                                      \
            int _c = tid + _i * 256;                                          \
            int _r = _c >> 2, _k8 = _c & 3;                                   \
            int _gr = row0 + _r; if (_gr >= M) _gr = M - 1;                   \
            CP_ASYNC16(_dA + (_r * PADS + _k8 * 8) * 2,                       \
                       A + (size_t)_gr * lda + _kc + _k8 * 8);                \
        }                                                                     \
        _Pragma("unroll")                                                     \
        for (int _i = 0; _i < 2; ++_i) {                                      \
            int _c = tid + _i * 256;                                          \
            int _r = _c >> 2, _k8 = _c & 3;                                   \
            CP_ASYNC16(_dB + (_r * PADS + _k8 * 8) * 2,                       \
                       B + (size_t)(col0 + _r) * ldb + _kc + _k8 * 8);        \
        }                                                                     \
    } while (0)

    LOAD_STAGE(0, 0); CP_COMMIT();
    LOAD_STAGE(1, 1); CP_COMMIT();
    LOAD_STAGE(2, 2); CP_COMMIT();

    for (int c = 0; c < NC; ++c) {
        const int buf = c & 3;
        CP_WAIT(2);
        __syncthreads();

        if (c + 3 < NC) LOAD_STAGE((c + 3) & 3, c + 3);
        CP_COMMIT();

        const uint32_t baseA = sbase + buf * (STAGE_ELEMS * 2);
        const uint32_t baseB = sbase + (NSTAGE + buf) * (STAGE_ELEMS * 2);

#pragma unroll
        for (int kk = 0; kk < 32; kk += 16) {
            uint32_t a[2][4];
#pragma unroll
            for (int mt = 0; mt < 2; mt++) {
                int r = wm * 32 + mt * 16 + (lane & 15);
                int kc = kk + ((lane & 16) ? 8 : 0);
                ldmatrix_x4(a[mt][0], a[mt][1], a[mt][2], a[mt][3],
                            baseA + (r * PADS + kc) * 2);
            }
            uint32_t b[8][2];
#pragma unroll
            for (int np = 0; np < 4; np++) {
                int n = wn * 64 + np * 16 + (lane & 7) + ((lane & 16) ? 8 : 0);
                int kc = kk + ((lane & 8) ? 8 : 0);
                ldmatrix_x4(b[2 * np][0], b[2 * np][1], b[2 * np + 1][0], b[2 * np + 1][1],
                            baseB + (n * PADS + kc) * 2);
            }
#pragma unroll
            for (int mt = 0; mt < 2; mt++)
#pragma unroll
                for (int nt = 0; nt < 8; nt++)
                    mma_f16(acc[mt][nt], a[mt], b[nt]);
        }
        __syncthreads();
    }

    // ---- epilogue ----
    float* outf = Cf;
    __half* outh = Ch;
    int ostride = N, coff = 0;
    int write_half = (mode == 1);
    if (mode == 2) {
        if (col0 < 256)      { outh = Ch; ostride = 256; coff = 0; write_half = 1; }
        else if (col0 < 512) { outf = C2; ostride = 256; coff = 256; }
        else                 { outf = C3; ostride = 128; coff = 512; }
    }

#pragma unroll
    for (int mt = 0; mt < 2; mt++) {
#pragma unroll
        for (int half_i = 0; half_i < 2; half_i++) {
            int r = row0 + wm * 32 + mt * 16 + (lane >> 2) + half_i * 8;
            if (r >= M) continue;
#pragma unroll
            for (int nt = 0; nt < 8; nt++) {
                int cidx = col0 + wn * 64 + nt * 8 + (lane & 3) * 2;
                float v0 = acc[mt][nt][half_i * 2 + 0] + bias[cidx];
                float v1 = acc[mt][nt][half_i * 2 + 1] + bias[cidx + 1];
                if (relu) { v0 = fmaxf(v0, 0.f); v1 = fmaxf(v1, 0.f); }
                if (write_half) {
                    __half2 hv;
                    hv.x = __float2half_rn(v0);
                    hv.y = __float2half_rn(v1);
                    *reinterpret_cast<__half2*>(outh + (size_t)r * ostride + (cidx - coff)) = hv;
                } else {
                    float2 o = make_float2(v0, v1);
                    *reinterpret_cast<float2*>(outf + (size_t)r * ostride + (cidx - coff)) = o;
                }
            }
        }
    }
#undef LOAD_STAGE
}

// ---------------- combined weight prep (single launch) ----------------
__device__ __forceinline__ void wtr1(const float* __restrict__ W, __half* __restrict__ Wt,
                                     int K_, int N_, int i)
{
    int k = i / N_, n = i % N_;
    Wt[(size_t)n * K_ + k] = __float2half_rn(W[i]);
}

__global__ void prep_kernel(const float* __restrict__ vW, const float* __restrict__ oW,
                            const float* __restrict__ aW, const float* __restrict__ uW,
                            const float* __restrict__ f1W, const float* __restrict__ f2W,
                            const float* __restrict__ vb, const float* __restrict__ ob,
                            const float* __restrict__ ab,
                            __half* __restrict__ wtp, __half* __restrict__ wtu,
                            __half* __restrict__ wtf1, __half* __restrict__ wtf2,
                            float* __restrict__ biasp)
{
    int i = blockIdx.x * blockDim.x + threadIdx.x;
    if (i < 65536)       { wtr1(vW, wtp, 256, 256, i); return; }
    i -= 65536;
    if (i < 65536)       { wtr1(oW, wtp + 256 * 256, 256, 256, i); return; }
    i -= 65536;
    if (i < 32768)       { wtr1(aW, wtp + 512 * 256, 256, 128, i); return; }
    i -= 32768;
    if (i < 65536)       { wtr1(uW, wtu, 256, 256, i); return; }
    i -= 65536;
    if (i < 262144)      { wtr1(f1W, wtf1, 256, 1024, i); return; }
    i -= 262144;
    if (i < 262144)      { wtr1(f2W, wtf2, 1024, 256, i); return; }
    i -= 262144;
    if (i < 256)         { biasp[i] = vb[i]; return; }
    if (i < 512)         { biasp[i] = ob[i - 256]; return; }
    if (i < 640)         { biasp[i] = ab[i - 512]; return; }
}

// ---------------- q = src + pos (fp32 + fp16), float4 ----------------
__global__ void add_split_kernel(const float* __restrict__ a, const float* __restrict__ b,
                                 float* __restrict__ q, __half* __restrict__ qh, int n4)
{
    int i = blockIdx.x * blockDim.x + threadIdx.x;
    if (i >= n4) return;
    float4 x = reinterpret_cast<const float4*>(a)[i];
    float4 y = reinterpret_cast<const float4*>(b)[i];
    x.x += y.x; x.y += y.y; x.z += y.z; x.w += y.w;
    reinterpret_cast<float4*>(q)[i] = x;
    __half2 h0 = __floats2half2_rn(x.x, x.y);
    __half2 h1 = __floats2half2_rn(x.z, x.w);
    uint2 hp;
    hp.x = *reinterpret_cast<uint32_t*>(&h0);
    hp.y = *reinterpret_cast<uint32_t*>(&h1);
    reinterpret_cast<uint2*>(qh)[i] = hp;
}

// ---------------- MSDA v3: fused softmax + float4 gathers ------------------
// block = token, warp = head.
// Phase 1: lane j=lane&15 precomputes point j (corner indices + softmax-scaled
//          bilinear weights; invalid corners -> weight 0).
// Phase 2: 2 passes x 8 points; lane group g=lane>>2 handles point p*8+g,
//          lane c4=lane&3 loads a float4 (8 channels). 4 corner loads/pass.
// Phase 3: shfl-xor tree over the 8 groups; lanes 0-3 write 16B each.
__global__ __launch_bounds__(256)
void msda_kernel(const __half* __restrict__ value, const float* __restrict__ offs,
                 const float* __restrict__ aw, const float* __restrict__ ref,
                 const int* __restrict__ shapes, const int* __restrict__ starts,
                 __half* __restrict__ outh)
{
    const int tok = blockIdx.x;
    const int h = threadIdx.x >> 5;
    const int lane = threadIdx.x & 31;
    const int j = lane & 15;
    const int b = tok / LIN;
    const int l = j >> 2;

    // ---- per-point precompute (duplicated in both 16-lane halves) ----
    const int Hl = shapes[l * 2 + 0];
    const int Wl = shapes[l * 2 + 1];
    const int st = starts[l];
    const float fW = (float)Wl, fH = (float)Hl;
    const float rx = ref[(size_t)tok * 8 + l * 2 + 0];
    const float ry = ref[(size_t)tok * 8 + l * 2 + 1];
    const float2 off = *reinterpret_cast<const float2*>(offs + (size_t)tok * 256 + h * 32 + 2 * j);

    float logit = aw[(size_t)tok * 128 + h * 16 + j];
    float m = logit;
#pragma unroll
    for (int o = 8; o; o >>= 1) m = fmaxf(m, __shfl_xor_sync(0xffffffffu, m, o, 16));
    float e = expf(logit - m);
    float s = e;
#pragma unroll
    for (int o = 8; o; o >>= 1) s += __shfl_xor_sync(0xffffffffu, s, o, 16);
    float wgt = e / s;

    float x = (rx + off.x / fW) * fW - 0.5f;
    float y = (ry + off.y / fH) * fH - 0.5f;
    float x0f = floorf(x), y0f = floorf(y);
    float dx = x - x0f, dy = y - y0f;
    int x0 = (int)x0f, y0 = (int)y0f;
    int x1 = x0 + 1, y1 = y0 + 1;

    bool xv0 = (x0 >= 0) & (x0 < Wl);
    bool xv1 = (x1 >= 0) & (x1 < Wl);
    bool yv0 = (y0 >= 0) & (y0 < Hl);
    bool yv1 = (y1 >= 0) & (y1 < Hl);

    float w00 = (xv0 && yv0) ? wgt * (1.f - dx) * (1.f - dy) : 0.f;
    float w10 = (xv1 && yv0) ? wgt * dx * (1.f - dy) : 0.f;
    float w01 = (xv0 && yv1) ? wgt * (1.f - dx) * dy : 0.f;
    float w11 = (xv1 && yv1) ? wgt * dx * dy : 0.f;

    int cx0 = min(max(x0, 0), Wl - 1), cx1 = min(max(x1, 0), Wl - 1);
    int cy0 = min(max(y0, 0), Hl - 1), cy1 = min(max(y1, 0), Hl - 1);
    const int base = b * LIN + st;
    int i00 = base + cy0 * Wl + cx0;
    int i10 = base + cy0 * Wl + cx1;
    int i01 = base + cy1 * Wl + cx0;
    int i11 = base + cy1 * Wl + cx1;

    // ---- gather: 2 passes x 8 points, float4 (8 channels) per lane ----
    const int g = lane >> 2;
    const int c4 = lane & 3;
    const __half* vch = value + h * DH + c4 * 8;
    float acc[8] = {0.f, 0.f, 0.f, 0.f, 0.f, 0.f, 0.f, 0.f};

#pragma unroll
    for (int p = 0; p < 2; p++) {
        const int pt = p * 8 + g;
        int a00 = __shfl_sync(0xffffffffu, i00, pt);
        int a10 = __shfl_sync(0xffffffffu, i10, pt);
        int a01 = __shfl_sync(0xffffffffu, i01, pt);
        int a11 = __shfl_sync(0xffffffffu, i11, pt);
        float u00 = __shfl_sync(0xffffffffu, w00, pt);
        float u10 = __shfl_sync(0xffffffffu, w10, pt);
        float u01 = __shfl_sync(0xffffffffu, w01, pt);
        float u11 = __shfl_sync(0xffffffffu, w11, pt);

        uint4 r00 = *reinterpret_cast<const uint4*>(vch + (size_t)a00 * DMODEL);
        uint4 r10 = *reinterpret_cast<const uint4*>(vch + (size_t)a10 * DMODEL);
        uint4 r01 = *reinterpret_cast<const uint4*>(vch + (size_t)a01 * DMODEL);
        uint4 r11 = *reinterpret_cast<const uint4*>(vch + (size_t)a11 * DMODEL);

#define ACC8(rv, u) do {                                                      \
        const __half2* _h = reinterpret_cast<const __half2*>(&(rv));          \
        _Pragma("unroll")                                                     \
        for (int _k = 0; _k < 4; _k++) {                                      \
            float2 _f = __half22float2(_h[_k]);                               \
            acc[2 * _k + 0] = fmaf(u, _f.x, acc[2 * _k + 0]);                 \
            acc[2 * _k + 1] = fmaf(u, _f.y, acc[2 * _k + 1]);                 \
        } } while (0)

        ACC8(r00, u00);
        ACC8(r10, u10);
        ACC8(r01, u01);
        ACC8(r11, u11);
#undef ACC8
    }

    // ---- reduce over the 8 point-groups ----
#pragma unroll
    for (int o = 4; o <= 16; o <<= 1) {
#pragma unroll
        for (int k = 0; k < 8; k++)
            acc[k] += __shfl_xor_sync(0xffffffffu, acc[k], o);
    }

    if (lane < 4) {
        __half2 h0 = __floats2half2_rn(acc[0], acc[1]);
        __half2 h1 = __floats2half2_rn(acc[2], acc[3]);
        __half2 h2 = __floats2half2_rn(acc[4], acc[5]);
        __half2 h3 = __floats2half2_rn(acc[6], acc[7]);
        uint4 o;
        o.x = *reinterpret_cast<uint32_t*>(&h0);
        o.y = *reinterpret_cast<uint32_t*>(&h1);
        o.z = *reinterpret_cast<uint32_t*>(&h2);
        o.w = *reinterpret_cast<uint32_t*>(&h3);
        *reinterpret_cast<uint4*>(outh + (size_t)tok * DMODEL + h * DH + lane * 8) = o;
    }
}

// ---------------- warp-per-token residual add + LayerNorm ------------------
// 8 warps/block, 1 token/warp, 8 channels/lane via 2x float4; no __syncthreads.
__global__ __launch_bounds__(256)
void add_ln_kernel(const float* __restrict__ a, const float* __restrict__ r,
                   const float* __restrict__ g, const float* __restrict__ bb,
                   float* __restrict__ out, __half* __restrict__ outh)
{
    const int tok = (blockIdx.x * blockDim.x + threadIdx.x) >> 5;
    const int lane = threadIdx.x & 31;
    if (tok >= MTOK) return;

    const float4* a4 = reinterpret_cast<const float4*>(a + (size_t)tok * DMODEL);
    const float4* r4 = reinterpret_cast<const float4*>(r + (size_t)tok * DMODEL);
    float4 v0 = a4[lane * 2 + 0], v1 = a4[lane * 2 + 1];
    float4 u0 = r4[lane * 2 + 0], u1 = r4[lane * 2 + 1];
    v0.x += u0.x; v0.y += u0.y; v0.z += u0.z; v0.w += u0.w;
    v1.x += u1.x; v1.y += u1.y; v1.z += u1.z; v1.w += u1.w;

    float s = v0.x + v0.y + v0.z + v0.w + v1.x + v1.y + v1.z + v1.w;
#pragma unroll
    for (int o = 16; o; o >>= 1) s += __shfl_xor_sync(0xffffffffu, s, o);
    float mean = s * (1.f / 256.f);

    float d0x = v0.x - mean, d0y = v0.y - mean, d0z = v0.z - mean, d0w = v0.w - mean;
    float d1x = v1.x - mean, d1y = v1.y - mean, d1z = v1.z - mean, d1w = v1.w - mean;
    float s2 = d0x * d0x + d0y * d0y + d0z * d0z + d0w * d0w
             + d1x * d1x + d1y * d1y + d1z * d1z + d1w * d1w;
#pragma unroll
    for (int o = 16; o; o >>= 1) s2 += __shfl_xor_sync(0xffffffffu, s2, o);
    float inv = rsqrtf(s2 * (1.f / 256.f) + 1e-5f);

    const float4* g4 = reinterpret_cast<const float4*>(g);
    const float4* b4 = reinterpret_cast<const float4*>(bb);
    float4 g0 = g4[lane * 2 + 0], g1 = g4[lane * 2 + 1];
    float4 bb0 = b4[lane * 2 + 0], bb1 = b4[lane * 2 + 1];

    float4 o0, o1;
    o0.x = d0x * inv * g0.x + bb0.x; o0.y = d0y * inv * g0.y + bb0.y;
    o0.z = d0z * inv * g0.z + bb0.z; o0.w = d0w * inv * g0.w + bb0.w;
    o1.x = d1x * inv * g1.x + bb1.x; o1.y = d1y * inv * g1.y + bb1.y;
    o1.z = d1z * inv * g1.z + bb1.z; o1.w = d1w * inv * g1.w + bb1.w;

    float4* out4 = reinterpret_cast<float4*>(out + (size_t)tok * DMODEL);
    out4[lane * 2 + 0] = o0;
    out4[lane * 2 + 1] = o1;

    if (outh) {
        __half2 h0 = __floats2half2_rn(o0.x, o0.y);
        __half2 h1 = __floats2half2_rn(o0.z, o0.w);
        __half2 h2 = __floats2half2_rn(o1.x, o1.y);
        __half2 h3 = __floats2half2_rn(o1.z, o1.w);
        uint4 hp;
        hp.x = *reinterpret_cast<uint32_t*>(&h0);
        hp.y = *reinterpret_cast<uint32_t*>(&h1);
        hp.z = *reinterpret_cast<uint32_t*>(&h2);
        hp.w = *reinterpret_cast<uint32_t*>(&h3);
        *reinterpret_cast<uint4*>(outh + (size_t)tok * DMODEL + lane * 8) = hp;
    }
}

// ---------------- launch ----------------
extern "C" void kernel_launch(void* const* d_in, const int* in_sizes, int n_in,
                              void* d_out, int out_size)
{
    const float* src    = (const float*)d_in[0];
    const float* pos    = (const float*)d_in[1];
    const float* refpts = (const float*)d_in[2];
    const int*   shapes = (const int*)  d_in[3];
    const int*   starts = (const int*)  d_in[4];
    const float* value_w = (const float*)d_in[5];
    const float* value_b = (const float*)d_in[6];
    const float* offs_w  = (const float*)d_in[7];
    const float* offs_b  = (const float*)d_in[8];
    const float* attn_w  = (const float*)d_in[9];
    const float* attn_b  = (const float*)d_in[10];
    const float* out_w   = (const float*)d_in[11];
    const float* out_b   = (const float*)d_in[12];
    const float* ln1_g   = (const float*)d_in[13];
    const float* ln1_b   = (const float*)d_in[14];
    const float* ff1_w   = (const float*)d_in[15];
    const float* ff1_b   = (const float*)d_in[16];
    const float* ff2_w   = (const float*)d_in[17];
    const float* ff2_b   = (const float*)d_in[18];
    const float* ln2_g   = (const float*)d_in[19];
    const float* ln2_b   = (const float*)d_in[20];
    float* outp = (float*)d_out;

    float *q, *offs, *aw, *src2, *x, *biasp;
    __half *qh, *value, *msdah, *xh, *ffh;
    __half *wtp, *wtu, *wtf1, *wtf2;
    cudaGetSymbolAddress((void**)&q,     g_q);
    cudaGetSymbolAddress((void**)&qh,    g_qh);
    cudaGetSymbolAddress((void**)&value, g_value);
    cudaGetSymbolAddress((void**)&offs,  g_offs);
    cudaGetSymbolAddress((void**)&aw,    g_aw);
    cudaGetSymbolAddress((void**)&msdah, g_msdah);
    cudaGetSymbolAddress((void**)&src2,  g_src2);
    cudaGetSymbolAddress((void**)&x,     g_x);
    cudaGetSymbolAddress((void**)&xh,    g_xh);
    cudaGetSymbolAddress((void**)&ffh,   g_ffh);
    cudaGetSymbolAddress((void**)&wtp,   g_wt_proj);
    cudaGetSymbolAddress((void**)&wtu,   g_wt_out);
    cudaGetSymbolAddress((void**)&wtf1,  g_wt_ff1);
    cudaGetSymbolAddress((void**)&wtf2,  g_wt_ff2);
    cudaGetSymbolAddress((void**)&biasp, g_bias_proj);

    cudaFuncSetAttribute(gemm_mma, cudaFuncAttributeMaxDynamicSharedMemorySize, GEMM_SMEM);

    const int M = MTOK;
    const int gy = (M + 127) / 128;

    // 0. all weight prep in one launch
    prep_kernel<<<(754304 + 255) / 256, 256>>>(value_w, offs_w, attn_w, out_w, ff1_w, ff2_w,
                                               value_b, offs_b, attn_b,
                                               wtp, wtu, wtf1, wtf2, biasp);

    // 1. q = src + pos
    add_split_kernel<<<(M * DMODEL / 4 + 255) / 256, 256>>>(src, pos, q, qh, M * DMODEL / 4);

    // 2. fused projections: [value(fp16) | offs | aw] = q @ Wp^T
    gemm_mma<<<dim3(5, gy), 256, GEMM_SMEM>>>(qh, 256, wtp, 256, biasp,
                                              nullptr, value, offs, aw, M, 256, 640, 0, 2);

    // 3. deformable sampling with fused softmax
    msda_kernel<<<M, 256>>>(value, offs, aw, refpts, shapes, starts, msdah);

    // 4. output projection: src2 = msda @ out_w + out_b
    gemm_mma<<<dim3(2, gy), 256, GEMM_SMEM>>>(msdah, 256, wtu, 256, out_b,
                                              src2, nullptr, nullptr, nullptr, M, 256, 256, 0, 0);

    // 5. x = LN(q + src2)  (+ fp16 copy)
    add_ln_kernel<<<(M * 32 + 255) / 256, 256>>>(q, src2, ln1_g, ln1_b, x, xh);

    // 6. ffh = relu(x @ ff1_w + ff1_b) -> fp16
    gemm_mma<<<dim3(8, gy), 256, GEMM_SMEM>>>(xh, 256, wtf1, 256, ff1_b,
                                              nullptr, ffh, nullptr, nullptr, M, 256, 1024, 1, 1);

    // 7. f = ffh @ ff2_w + ff2_b  (into 'offs' buffer)
    gemm_mma<<<dim3(2, gy), 256, GEMM_SMEM>>>(ffh, 1024, wtf2, 1024, ff2_b,
                                              offs, nullptr, nullptr, nullptr, M, 1024, 256, 0, 0);

    // 8. out = LN(x + f)
    add_ln_kernel<<<(M * 32 + 255) / 256, 256>>>(x, offs, ln2_g, ln2_b, outp, nullptr);
}